// round 1
// baseline (speedup 1.0000x reference)
#include <cuda_runtime.h>
#include <cstddef>
#include <cstdint>

// ---------------- problem constants ----------------
constexpr int Nn  = 100000;
constexpr int Mm  = 12500;
constexpr int E0n = 1600000;
constexpr int E1n = 400000;

constexpr size_t F_N64 = (size_t)Nn * 64;
constexpr size_t F_M64 = (size_t)Mm * 64;

// arena layout (floats); keep everything 16B-aligned (all sizes padded to mult of 16 floats)
constexpr size_t pad16(size_t x) { return (x + 15) & ~(size_t)15; }
constexpr size_t OFF_F1   = 0;
constexpr size_t OFF_F2   = OFF_F1  + F_N64;
constexpr size_t OFF_F21  = OFF_F2  + F_N64;
constexpr size_t OFF_F5   = OFF_F21 + F_N64;
constexpr size_t OFF_F6   = OFF_F5  + F_N64;
constexpr size_t OFF_NP   = OFF_F6  + F_N64;
constexpr size_t OFF_AGG  = OFF_NP  + F_N64;
constexpr size_t OFF_REL  = OFF_AGG + F_N64;
constexpr size_t OFF_MA   = OFF_REL + pad16((size_t)Nn * 3);
constexpr size_t OFF_MB   = OFF_MA  + F_M64;
constexpr size_t OFF_MNP  = OFF_MB  + F_M64;
constexpr size_t OFF_MAGG = OFF_MNP + F_M64;
// int region (reinterpret as int*)
constexpr size_t OFF_CNT0  = OFF_MAGG + F_M64;
constexpr size_t OFF_OFFS0 = OFF_CNT0  + pad16(Nn);
constexpr size_t OFF_CUR0  = OFF_OFFS0 + pad16(Nn + 1);
constexpr size_t OFF_CSR0  = OFF_CUR0  + pad16(Nn);
constexpr size_t OFF_CNT1  = OFF_CSR0  + pad16(E0n);
constexpr size_t OFF_OFFS1 = OFF_CNT1  + pad16(Mm);
constexpr size_t OFF_CUR1  = OFF_OFFS1 + pad16(Mm + 1);
constexpr size_t OFF_CSR1  = OFF_CUR1  + pad16(Mm);
constexpr size_t ARENA_SZ  = OFF_CSR1  + pad16(E1n);

__device__ __align__(256) static float g_arena[ARENA_SZ];

// ---------------- small kernels ----------------

__global__ void k_rel(const float* __restrict__ points, const float* __restrict__ centers,
                      const int* __restrict__ labels, float* __restrict__ rel, int n) {
    int i = blockIdx.x * blockDim.x + threadIdx.x;
    if (i < n) {
        int l = labels[i];
        rel[3*i+0] = points[3*i+0] - centers[3*l+0];
        rel[3*i+1] = points[3*i+1] - centers[3*l+1];
        rel[3*i+2] = points[3*i+2] - centers[3*l+2];
    }
}

// f1 = relu([features(4), rel(3)] @ W_fe(7x64) + b_fe)
__global__ void k_f1(const float* __restrict__ feats, const float* __restrict__ rel,
                     const float* __restrict__ W, const float* __restrict__ b,
                     float* __restrict__ out, int n) {
    __shared__ float sW[7 * 64];
    int tid = threadIdx.x;
    for (int i = tid; i < 7 * 64; i += 256) sW[i] = W[i];
    __syncthreads();
    int j = tid & 63;
    int i = blockIdx.x * 4 + (tid >> 6);
    if (i < n) {
        float acc = b[j];
        #pragma unroll
        for (int k = 0; k < 4; k++) acc = fmaf(feats[4*i+k], sW[k*64+j], acc);
        #pragma unroll
        for (int k = 0; k < 3; k++) acc = fmaf(rel[3*i+k], sW[(4+k)*64+j], acc);
        out[(size_t)i*64 + j] = fmaxf(acc, 0.f);
    }
}

// histogram of dst
__global__ void k_hist(const int* __restrict__ edges, int* __restrict__ cnt, int E) {
    int e = blockIdx.x * blockDim.x + threadIdx.x;
    if (e < E) atomicAdd(&cnt[edges[2*e+1]], 1);
}

// single-block chunked exclusive scan; writes offs[0..n]
__global__ void k_scan(const int* __restrict__ cnt, int* __restrict__ offs, int n) {
    __shared__ int sums[1024];
    int t = threadIdx.x;
    int chunk = (n + 1023) / 1024;
    int begin = t * chunk;
    int end = begin + chunk; if (end > n) end = n; if (begin > n) begin = n;
    int s = 0;
    for (int i = begin; i < end; i++) s += cnt[i];
    sums[t] = s;
    __syncthreads();
    for (int off = 1; off < 1024; off <<= 1) {
        int v = (t >= off) ? sums[t - off] : 0;
        __syncthreads();
        sums[t] += v;
        __syncthreads();
    }
    int run = (t == 0) ? 0 : sums[t - 1];
    for (int i = begin; i < end; i++) { offs[i] = run; run += cnt[i]; }
    if (t == 1023) offs[n] = sums[1023];
}

__global__ void k_scatter(const int* __restrict__ edges, int* __restrict__ cur,
                          int* __restrict__ csrc, int E) {
    int e = blockIdx.x * blockDim.x + threadIdx.x;
    if (e < E) {
        int d = edges[2*e+1];
        int p = atomicAdd(&cur[d], 1);
        csrc[p] = edges[2*e];
    }
}

// CSR segment-max aggregation with fused per-edge 3x64 positional MLP.
// warp per dst node; np already contains feat@We_feat + be.
__global__ void k_agg(const int* __restrict__ offs, const int* __restrict__ csrc,
                      const float* __restrict__ pos, const float* __restrict__ np,
                      const float* __restrict__ Wp, float* __restrict__ agg, int n) {
    int lane = threadIdx.x & 31;
    int d = (blockIdx.x * blockDim.x + threadIdx.x) >> 5;
    if (d >= n) return;
    float w0a = Wp[lane],      w1a = Wp[64+lane],  w2a = Wp[128+lane];
    float w0b = Wp[32+lane],   w1b = Wp[96+lane],  w2b = Wp[160+lane];
    int s0 = offs[d], s1 = offs[d+1];
    float px = pos[3*d], py = pos[3*d+1], pz = pos[3*d+2];
    float aa = 0.f, ab = 0.f;
    int s = (s0 < s1) ? csrc[s0] : 0;
    for (int e = s0; e < s1; e++) {
        int snext = (e + 1 < s1) ? csrc[e+1] : 0;
        float dx = pos[3*s]   - px;
        float dy = pos[3*s+1] - py;
        float dz = pos[3*s+2] - pz;
        float va = np[(size_t)s*64 + lane]      + fmaf(dx, w0a, fmaf(dy, w1a, dz*w2a));
        float vb = np[(size_t)s*64 + 32 + lane] + fmaf(dx, w0b, fmaf(dy, w1b, dz*w2b));
        aa = fmaxf(aa, va);   // aa starts at 0 -> relu + (neginf->0) implied
        ab = fmaxf(ab, vb);
        s = snext;
    }
    agg[(size_t)d*64 + lane]      = aa;
    agg[(size_t)d*64 + 32 + lane] = ab;
}

// generic (n x 64) @ (64 x 64) with optional rel-extension rows (W[64..66]),
// optional gather index on input rows, optional relu, up to 2 residual adds.
template<bool RELU, bool HAS_REL, bool GATHER, int NRES>
__global__ void k_linear64(const float* __restrict__ in, const int* __restrict__ gidx,
                           const float* __restrict__ W, const float* __restrict__ b,
                           const float* __restrict__ rel,
                           const float* __restrict__ res1, const float* __restrict__ res2,
                           float* __restrict__ out, int n) {
    __shared__ float sW[64][64];
    __shared__ float sA[64][68];   // transposed A tile: sA[k][row], stride 68 keeps 16B align
    __shared__ float sWr[3][64];
    __shared__ float sRel[64][3];
    int tid = threadIdx.x;
    for (int i = tid; i < 4096; i += 256) sW[i >> 6][i & 63] = W[i];
    if (HAS_REL)
        for (int i = tid; i < 192; i += 256) sWr[i / 64][i % 64] = W[4096 + i];
    int row0 = blockIdx.x * 64;
    for (int i = tid; i < 4096; i += 256) {
        int r = i >> 6, k = i & 63;
        int row = row0 + r;
        float v = 0.f;
        if (row < n) {
            int sr = GATHER ? gidx[row] : row;
            v = in[(size_t)sr * 64 + k];
        }
        sA[k][r] = v;
    }
    if (HAS_REL) {
        for (int i = tid; i < 192; i += 256) {
            int r = i / 3, c = i % 3;
            sRel[r][c] = (row0 + r < n) ? rel[(size_t)(row0 + r) * 3 + c] : 0.f;
        }
    }
    __syncthreads();
    int tx = tid & 15, ty = tid >> 4;   // cols tx*4.., rows ty*4..
    float acc[4][4];
    #pragma unroll
    for (int r = 0; r < 4; r++)
        #pragma unroll
        for (int c = 0; c < 4; c++) acc[r][c] = 0.f;
    #pragma unroll 16
    for (int k = 0; k < 64; k++) {
        const float4 bv = *reinterpret_cast<const float4*>(&sW[k][tx * 4]);
        const float4 av = *reinterpret_cast<const float4*>(&sA[k][ty * 4]);
        acc[0][0] = fmaf(av.x, bv.x, acc[0][0]); acc[0][1] = fmaf(av.x, bv.y, acc[0][1]);
        acc[0][2] = fmaf(av.x, bv.z, acc[0][2]); acc[0][3] = fmaf(av.x, bv.w, acc[0][3]);
        acc[1][0] = fmaf(av.y, bv.x, acc[1][0]); acc[1][1] = fmaf(av.y, bv.y, acc[1][1]);
        acc[1][2] = fmaf(av.y, bv.z, acc[1][2]); acc[1][3] = fmaf(av.y, bv.w, acc[1][3]);
        acc[2][0] = fmaf(av.z, bv.x, acc[2][0]); acc[2][1] = fmaf(av.z, bv.y, acc[2][1]);
        acc[2][2] = fmaf(av.z, bv.z, acc[2][2]); acc[2][3] = fmaf(av.z, bv.w, acc[2][3]);
        acc[3][0] = fmaf(av.w, bv.x, acc[3][0]); acc[3][1] = fmaf(av.w, bv.y, acc[3][1]);
        acc[3][2] = fmaf(av.w, bv.z, acc[3][2]); acc[3][3] = fmaf(av.w, bv.w, acc[3][3]);
    }
    const float4 bb = *reinterpret_cast<const float4*>(&b[tx * 4]);
    #pragma unroll
    for (int r = 0; r < 4; r++) {
        int lrow = ty * 4 + r;
        int row = row0 + lrow;
        if (row >= n) continue;
        float v[4] = { acc[r][0] + bb.x, acc[r][1] + bb.y, acc[r][2] + bb.z, acc[r][3] + bb.w };
        if (HAS_REL) {
            float rx = sRel[lrow][0], ry = sRel[lrow][1], rz = sRel[lrow][2];
            #pragma unroll
            for (int c = 0; c < 4; c++) {
                int col = tx * 4 + c;
                v[c] += rx * sWr[0][col] + ry * sWr[1][col] + rz * sWr[2][col];
            }
        }
        if (RELU) {
            #pragma unroll
            for (int c = 0; c < 4; c++) v[c] = fmaxf(v[c], 0.f);
        }
        size_t base = (size_t)row * 64 + tx * 4;
        if (NRES >= 1) {
            const float4 r1 = *reinterpret_cast<const float4*>(&res1[base]);
            v[0] += r1.x; v[1] += r1.y; v[2] += r1.z; v[3] += r1.w;
        }
        if (NRES >= 2) {
            const float4 r2 = *reinterpret_cast<const float4*>(&res2[base]);
            v[0] += r2.x; v[1] += r2.y; v[2] += r2.z; v[3] += r2.w;
        }
        float4 o = { v[0], v[1], v[2], v[3] };
        *reinterpret_cast<float4*>(&out[base]) = o;
    }
}

// c[labels[i]] += h[i]
__global__ void k_segsum(const float* __restrict__ h, const int* __restrict__ labels,
                         float* __restrict__ c, int n) {
    int idx = blockIdx.x * blockDim.x + threadIdx.x;
    if (idx < n * 64) {
        int i = idx >> 6, j = idx & 63;
        atomicAdd(&c[(size_t)labels[i] * 64 + j], h[idx]);
    }
}

// out(n x 8) = in(n x 64) @ Wc(64 x 8) + bc
__global__ void k_cls(const float* __restrict__ in, const float* __restrict__ W,
                      const float* __restrict__ b, float* __restrict__ out, int n) {
    __shared__ float sW[64 * 8];
    __shared__ float sIn[32][65];
    int tid = threadIdx.x;
    for (int i = tid; i < 512; i += 256) sW[i] = W[i];
    int node0 = blockIdx.x * 32;
    for (int i = tid; i < 32 * 64; i += 256) {
        int r = i >> 6, k = i & 63;
        sIn[r][k] = (node0 + r < n) ? in[(size_t)(node0 + r) * 64 + k] : 0.f;
    }
    __syncthreads();
    int r = tid >> 3, cls = tid & 7;
    int row = node0 + r;
    if (row < n) {
        float acc = b[cls];
        #pragma unroll
        for (int k = 0; k < 64; k++) acc = fmaf(sIn[r][k], sW[k * 8 + cls], acc);
        out[(size_t)row * 8 + cls] = acc;
    }
}

// ---------------- host orchestration ----------------

extern "C" void kernel_launch(void* const* d_in, const int* in_sizes, int n_in,
                              void* d_out, int out_size) {
    (void)in_sizes; (void)n_in; (void)out_size;
    float* A = nullptr;
    cudaGetSymbolAddress((void**)&A, g_arena);

    float* f1   = A + OFF_F1;
    float* f2   = A + OFF_F2;
    float* f21  = A + OFF_F21;
    float* f5   = A + OFF_F5;
    float* f6   = A + OFF_F6;
    float* np   = A + OFF_NP;
    float* agg  = A + OFF_AGG;
    float* rel  = A + OFF_REL;
    float* mA   = A + OFF_MA;
    float* mB   = A + OFF_MB;
    float* mnp  = A + OFF_MNP;
    float* magg = A + OFF_MAGG;
    int* cnt0  = (int*)(A + OFF_CNT0);
    int* offs0 = (int*)(A + OFF_OFFS0);
    int* cur0  = (int*)(A + OFF_CUR0);
    int* csr0  = (int*)(A + OFF_CSR0);
    int* cnt1  = (int*)(A + OFF_CNT1);
    int* offs1 = (int*)(A + OFF_OFFS1);
    int* cur1  = (int*)(A + OFF_CUR1);
    int* csr1  = (int*)(A + OFF_CSR1);

    const float* features = (const float*)d_in[0];
    const float* points   = (const float*)d_in[1];
    const float* centers  = (const float*)d_in[2];
    const int*   l0       = (const int*)d_in[3];
    const int*   l1       = (const int*)d_in[4];
    const int*   labels   = (const int*)d_in[5];
    const float* W_fe     = (const float*)d_in[6];
    const float* b_fe     = (const float*)d_in[7];
    const float* mini_We  = (const float*)d_in[8];
    const float* mini_be  = (const float*)d_in[9];
    const float* mini_Wu  = (const float*)d_in[10];
    const float* mini_bu  = (const float*)d_in[11];
    const float* W_m1     = (const float*)d_in[12];
    const float* b_m1     = (const float*)d_in[13];
    const float* W_m2     = (const float*)d_in[14];
    const float* b_m2     = (const float*)d_in[15];
    const float* gnn_We   = (const float*)d_in[16];
    const float* gnn_be   = (const float*)d_in[17];
    const float* gnn_Wu   = (const float*)d_in[18];
    const float* gnn_bu   = (const float*)d_in[19];
    const float* W_l      = (const float*)d_in[20];
    const float* b_l      = (const float*)d_in[21];
    const float* W_c      = (const float*)d_in[22];
    const float* b_c      = (const float*)d_in[23];
    float* out = (float*)d_out;

    const int TILES_N = (Nn + 63) / 64;   // 1563
    const int TILES_M = (Mm + 63) / 64;   // 196

    // ---- CSR builds (dst-sorted) ----
    cudaMemsetAsync(cnt0, 0, Nn * sizeof(int));
    cudaMemsetAsync(cnt1, 0, Mm * sizeof(int));
    k_hist<<<(E0n + 255) / 256, 256>>>(l0, cnt0, E0n);
    k_hist<<<(E1n + 255) / 256, 256>>>(l1, cnt1, E1n);
    k_scan<<<1, 1024>>>(cnt0, offs0, Nn);
    k_scan<<<1, 1024>>>(cnt1, offs1, Mm);
    cudaMemcpyAsync(cur0, offs0, Nn * sizeof(int), cudaMemcpyDeviceToDevice);
    cudaMemcpyAsync(cur1, offs1, Mm * sizeof(int), cudaMemcpyDeviceToDevice);
    k_scatter<<<(E0n + 255) / 256, 256>>>(l0, cur0, csr0, E0n);
    k_scatter<<<(E1n + 255) / 256, 256>>>(l1, cur1, csr1, E1n);

    // ---- rel + feature encoder ----
    k_rel<<<(Nn + 255) / 256, 256>>>(points, centers, labels, rel, Nn);
    k_f1<<<(Nn + 3) / 4, 256>>>(features, rel, W_fe, b_fe, f1, Nn);

    // ---- GNN on N ----
    auto gnnN = [&](int l, const float* fin, float* fout, const float* extra) {
        const float* We = mini_We + (size_t)l * 67 * 64;
        const float* be = mini_be + (size_t)l * 64;
        const float* Wu = mini_Wu + (size_t)l * 64 * 64;
        const float* bu = mini_bu + (size_t)l * 64;
        k_linear64<false,false,false,0><<<TILES_N,256>>>(fin, nullptr, We + 192, be,
                                                         nullptr, nullptr, nullptr, np, Nn);
        k_agg<<<(Nn + 7) / 8, 256>>>(offs0, csr0, points, np, We, agg, Nn);
        if (extra)
            k_linear64<true,false,false,2><<<TILES_N,256>>>(agg, nullptr, Wu, bu,
                                                            nullptr, fin, extra, fout, Nn);
        else
            k_linear64<true,false,false,1><<<TILES_N,256>>>(agg, nullptr, Wu, bu,
                                                            nullptr, fin, nullptr, fout, Nn);
    };
    auto gnnM = [&](int l, const float* fin, float* fout) {
        const float* We = gnn_We + (size_t)l * 67 * 64;
        const float* be = gnn_be + (size_t)l * 64;
        const float* Wu = gnn_Wu + (size_t)l * 64 * 64;
        const float* bu = gnn_bu + (size_t)l * 64;
        k_linear64<false,false,false,0><<<TILES_M,256>>>(fin, nullptr, We + 192, be,
                                                         nullptr, nullptr, nullptr, mnp, Mm);
        k_agg<<<(Mm + 7) / 8, 256>>>(offs1, csr1, centers, mnp, We, magg, Mm);
        k_linear64<true,false,false,1><<<TILES_M,256>>>(magg, nullptr, Wu, bu,
                                                        nullptr, fin, nullptr, fout, Mm);
    };

    gnnN(0, f1, f2, nullptr);    // f2
    gnnN(1, f2, f21, nullptr);   // f2_1

    // h = relu([f2_1, rel] @ W_m1 + b_m1) -> np buffer
    k_linear64<true,true,false,0><<<TILES_N,256>>>(f21, nullptr, W_m1, b_m1,
                                                   rel, nullptr, nullptr, np, Nn);
    // c = segment_sum(h, labels)
    cudaMemsetAsync(mA, 0, F_M64 * sizeof(float));
    k_segsum<<<(Nn * 64 + 255) / 256, 256>>>(np, labels, mA, Nn);
    // f3 = relu(c @ W_m2 + b_m2)
    k_linear64<true,false,false,0><<<TILES_M,256>>>(mA, nullptr, W_m2, b_m2,
                                                    nullptr, nullptr, nullptr, mB, Mm);
    gnnM(0, mB, mA);   // f4
    gnnM(1, mA, mB);   // f4_1

    // f5 = relu([f4_1[labels], rel] @ W_l + b_l)
    k_linear64<true,true,true,0><<<TILES_N,256>>>(mB, labels, W_l, b_l,
                                                  rel, nullptr, nullptr, f5, Nn);

    gnnN(2, f5, f6, f21);   // f6 = gnn(f5) + f2_1
    gnnN(3, f6, f5, f2);    // final = gnn(f6) + f2   (reuse f5 buffer)

    k_cls<<<(Nn + 31) / 32, 256>>>(f5, W_c, b_c, out, Nn);
}

// round 3
// speedup vs baseline: 1.0391x; 1.0391x over previous
#include <cuda_runtime.h>
#include <cstddef>
#include <cstdint>

// ---------------- problem constants ----------------
constexpr int Nn  = 100000;
constexpr int Mm  = 12500;
constexpr int E0n = 1600000;
constexpr int E1n = 400000;

constexpr size_t F_N64 = (size_t)Nn * 64;
constexpr size_t F_M64 = (size_t)Mm * 64;
constexpr size_t pad16(size_t x) { return (x + 15) & ~(size_t)15; }

// arena (floats)
constexpr size_t OFF_F1   = 0;
constexpr size_t OFF_F2   = OFF_F1  + F_N64;
constexpr size_t OFF_F21  = OFF_F2  + F_N64;
constexpr size_t OFF_F5   = OFF_F21 + F_N64;
constexpr size_t OFF_F6   = OFF_F5  + F_N64;
constexpr size_t OFF_NP   = OFF_F6  + F_N64;
constexpr size_t OFF_AGG  = OFF_NP  + F_N64;
constexpr size_t OFF_REL  = OFF_AGG + F_N64;
constexpr size_t OFF_MA   = OFF_REL + pad16((size_t)Nn * 3);
constexpr size_t OFF_MB   = OFF_MA  + F_M64;
constexpr size_t OFF_MNP  = OFF_MB  + F_M64;
constexpr size_t OFF_MAGG = OFF_MNP + F_M64;
// int region
constexpr size_t OFF_CNT0  = OFF_MAGG + F_M64;
constexpr size_t OFF_CNT1  = OFF_CNT0  + pad16(Nn);
constexpr size_t OFF_CNTL  = OFF_CNT1  + pad16(Mm);
constexpr size_t OFF_OFFS0 = OFF_CNTL  + pad16(Mm);
constexpr size_t OFF_CUR0  = OFF_OFFS0 + pad16(Nn + 1);
constexpr size_t OFF_CSR0  = OFF_CUR0  + pad16(Nn);
constexpr size_t OFF_OFFS1 = OFF_CSR0  + pad16(E0n);
constexpr size_t OFF_CUR1  = OFF_OFFS1 + pad16(Mm + 1);
constexpr size_t OFF_CSR1  = OFF_CUR1  + pad16(Mm);
constexpr size_t OFF_OFFSL = OFF_CSR1  + pad16(E1n);
constexpr size_t OFF_CURL  = OFF_OFFSL + pad16(Mm + 1);
constexpr size_t OFF_CSRL  = OFF_CURL  + pad16(Mm);
constexpr size_t ARENA_SZ  = OFF_CSRL  + pad16(Nn);

__device__ __align__(256) static float g_arena[ARENA_SZ];

// ---------------- helpers ----------------
__device__ __forceinline__ void ffma2(unsigned long long& d, unsigned long long a, unsigned long long b) {
    asm("fma.rn.f32x2 %0, %1, %2, %0;" : "+l"(d) : "l"(a), "l"(b));
}
__device__ __forceinline__ float2 up2(unsigned long long x) {
    float2 f;
    asm("mov.b64 {%0, %1}, %2;" : "=f"(f.x), "=f"(f.y) : "l"(x));
    return f;
}

// ---------------- CSR build ----------------
__global__ void k_hist(const int2* __restrict__ edges, int* __restrict__ cnt, int E) {
    int e = blockIdx.x * blockDim.x + threadIdx.x;
    if (e < E) atomicAdd(&cnt[edges[e].y], 1);
}
__global__ void k_histL(const int* __restrict__ lab, int* __restrict__ cnt, int n) {
    int i = blockIdx.x * blockDim.x + threadIdx.x;
    if (i < n) atomicAdd(&cnt[lab[i]], 1);
}
// 3 independent scans in one launch; also writes cur
__global__ void k_scan3(const int* c0, int* o0, int* u0, int n0,
                        const int* c1, int* o1, int* u1, int n1,
                        const int* c2, int* o2, int* u2, int n2) {
    const int* cnt; int* offs; int* cur; int n;
    if (blockIdx.x == 0) { cnt = c0; offs = o0; cur = u0; n = n0; }
    else if (blockIdx.x == 1) { cnt = c1; offs = o1; cur = u1; n = n1; }
    else { cnt = c2; offs = o2; cur = u2; n = n2; }
    __shared__ int sums[1024];
    int t = threadIdx.x;
    int chunk = (n + 1023) / 1024;
    int begin = t * chunk;
    int end = begin + chunk; if (end > n) end = n; if (begin > n) begin = n;
    int s = 0;
    for (int i = begin; i < end; i++) s += cnt[i];
    sums[t] = s;
    __syncthreads();
    for (int off = 1; off < 1024; off <<= 1) {
        int v = (t >= off) ? sums[t - off] : 0;
        __syncthreads();
        sums[t] += v;
        __syncthreads();
    }
    int run = (t == 0) ? 0 : sums[t - 1];
    for (int i = begin; i < end; i++) { offs[i] = run; cur[i] = run; run += cnt[i]; }
    if (t == 1023) offs[n] = sums[1023];
}
__global__ void k_scatter(const int2* __restrict__ edges, int* __restrict__ cur,
                          int* __restrict__ csrc, int E) {
    int e = blockIdx.x * blockDim.x + threadIdx.x;
    if (e < E) {
        int2 ed = edges[e];
        int p = atomicAdd(&cur[ed.y], 1);
        csrc[p] = ed.x;
    }
}
__global__ void k_scatterL(const int* __restrict__ lab, int* __restrict__ cur,
                           int* __restrict__ idx, int n) {
    int i = blockIdx.x * blockDim.x + threadIdx.x;
    if (i < n) {
        int p = atomicAdd(&cur[lab[i]], 1);
        idx[p] = i;
    }
}

// ---------------- edge aggregation (CSR max, fused positional part) ----------------
__global__ void k_agg(const int* __restrict__ offs, const int* __restrict__ csrc,
                      const float* __restrict__ pos, const float2* __restrict__ np2,
                      const float* __restrict__ Wp, float2* __restrict__ agg, int n) {
    int lane = threadIdx.x & 31;
    int d = (blockIdx.x * blockDim.x + threadIdx.x) >> 5;
    if (d >= n) return;
    int c0 = 2 * lane, c1 = c0 + 1;
    float w0x = Wp[c0],       w0y = Wp[c1];
    float w1x = Wp[64 + c0],  w1y = Wp[64 + c1];
    float w2x = Wp[128 + c0], w2y = Wp[128 + c1];
    int s0 = offs[d], s1 = offs[d + 1];
    float px = pos[3 * d], py = pos[3 * d + 1], pz = pos[3 * d + 2];
    float ax = 0.f, ay = 0.f;
    int s = (s0 < s1) ? csrc[s0] : 0;
    for (int e = s0; e < s1; e++) {
        int sn = (e + 1 < s1) ? csrc[e + 1] : 0;
        float dx = pos[3 * s]     - px;
        float dy = pos[3 * s + 1] - py;
        float dz = pos[3 * s + 2] - pz;
        float2 v = np2[(size_t)s * 32 + lane];
        float pa = fmaf(dx, w0x, fmaf(dy, w1x, dz * w2x));
        float pb = fmaf(dx, w0y, fmaf(dy, w1y, dz * w2y));
        ax = fmaxf(ax, v.x + pa);
        ay = fmaxf(ay, v.y + pb);
        s = sn;
    }
    agg[(size_t)d * 32 + lane] = make_float2(ax, ay);
}

// segment sum via label-CSR: warp per cluster
__global__ void k_segsum(const int* __restrict__ offs, const int* __restrict__ idx,
                         const float2* __restrict__ h, float2* __restrict__ c, int m) {
    int lane = threadIdx.x & 31;
    int d = (blockIdx.x * blockDim.x + threadIdx.x) >> 5;
    if (d >= m) return;
    int s0 = offs[d], s1 = offs[d + 1];
    float sx = 0.f, sy = 0.f;
    for (int e = s0; e < s1; e++) {
        int p = idx[e];
        float2 v = h[(size_t)p * 32 + lane];
        sx += v.x; sy += v.y;
    }
    c[(size_t)d * 32 + lane] = make_float2(sx, sy);
}

// ---------------- unified GEMM kernel ----------------
// out1 = relu(A @ W1[0:K1] + b1 (+ rel @ W1[K1:K1+3])) (+res1)(+res2)
// FUSE==1: out2 = [out1 (,rel)] @ W2 + b2 (optional relu2)
// FUSE==2: out2 = out1 @ W2(64x8) + b2  (classifier)
// A tile is staged in dynamic smem in duplicated {a,a} float2 form,
// chunked KC k-rows at a time so total smem stays < 48KB.
template<int K1, bool GATHER, bool MAKEREL, bool REL1, int NRES, bool STORE1,
         int FUSE, bool REL2, bool RELU2>
__global__ __launch_bounds__(256)
void k_gemm(const float* __restrict__ in, const int* __restrict__ gidx,
            const float* __restrict__ points, const float* __restrict__ centers,
            const int* __restrict__ labels, float* __restrict__ relg,
            const float* __restrict__ W1, const float* __restrict__ b1,
            const float* __restrict__ res1, const float* __restrict__ res2,
            float* __restrict__ out1,
            const float* __restrict__ W2, const float* __restrict__ b2,
            float* __restrict__ out2, int n) {
    extern __shared__ float2 sAd[];          // [KC][66] duplicated A: {a,a}  (KC<=32)
    __shared__ float sW[64 * 64];
    __shared__ float sWr1[192];
    __shared__ float sWr2[192];
    __shared__ float sRel[192];

    constexpr int KC = (K1 < 32) ? K1 : 32;

    const int tid = threadIdx.x;
    const int row0 = blockIdx.x * 64;

    // weights (first GEMM)
    for (int i = tid; i < K1 * 64; i += 256) sW[i] = W1[i];
    if (REL1)
        for (int i = tid; i < 192; i += 256) sWr1[i] = W1[K1 * 64 + i];
    // rel
    if (MAKEREL) {
        if (tid < 64) {
            int row = row0 + tid;
            float rx = 0.f, ry = 0.f, rz = 0.f;
            if (row < n) {
                int l = labels[row];
                rx = points[3 * row]     - centers[3 * l];
                ry = points[3 * row + 1] - centers[3 * l + 1];
                rz = points[3 * row + 2] - centers[3 * l + 2];
                relg[3 * row] = rx; relg[3 * row + 1] = ry; relg[3 * row + 2] = rz;
            }
            sRel[tid * 3] = rx; sRel[tid * 3 + 1] = ry; sRel[tid * 3 + 2] = rz;
        }
    } else if (REL1 || REL2) {
        if (tid < 64) {
            int row = row0 + tid;
            float rx = 0.f, ry = 0.f, rz = 0.f;
            if (row < n) { rx = relg[3 * row]; ry = relg[3 * row + 1]; rz = relg[3 * row + 2]; }
            sRel[tid * 3] = rx; sRel[tid * 3 + 1] = ry; sRel[tid * 3 + 2] = rz;
        }
    }

    const int tx = tid & 15, ty = tid >> 4;
    unsigned long long acc[4][2];
    #pragma unroll
    for (int r = 0; r < 4; r++) { acc[r][0] = 0ULL; acc[r][1] = 0ULL; }

    // ---- first GEMM, A chunked over K ----
    for (int kc = 0; kc < K1; kc += KC) {
        __syncthreads();   // previous chunk fully consumed (also covers W/rel loads on kc==0)
        for (int i = tid; i < KC * 64; i += 256) {
            int r = i / KC, k = i - r * KC;
            int row = row0 + r;
            float v = 0.f;
            if (row < n) {
                int sr = GATHER ? gidx[row] : row;
                v = in[(size_t)sr * K1 + kc + k];
            }
            sAd[k * 66 + r] = make_float2(v, v);
        }
        __syncthreads();
        #pragma unroll 16
        for (int k = 0; k < KC; k++) {
            const ulonglong2 a01 = *reinterpret_cast<const ulonglong2*>(&sAd[k * 66 + ty * 4]);
            const ulonglong2 a23 = *reinterpret_cast<const ulonglong2*>(&sAd[k * 66 + ty * 4 + 2]);
            const ulonglong2 bv  = *reinterpret_cast<const ulonglong2*>(&sW[(kc + k) * 64 + tx * 4]);
            ffma2(acc[0][0], a01.x, bv.x); ffma2(acc[0][1], a01.x, bv.y);
            ffma2(acc[1][0], a01.y, bv.x); ffma2(acc[1][1], a01.y, bv.y);
            ffma2(acc[2][0], a23.x, bv.x); ffma2(acc[2][1], a23.x, bv.y);
            ffma2(acc[3][0], a23.y, bv.x); ffma2(acc[3][1], a23.y, bv.y);
        }
    }

    // ---- epilogue 1 ----
    float v[4][4];
    const float b1x = b1[tx * 4], b1y = b1[tx * 4 + 1], b1z = b1[tx * 4 + 2], b1w = b1[tx * 4 + 3];
    #pragma unroll
    for (int r = 0; r < 4; r++) {
        float2 p0 = up2(acc[r][0]), p1 = up2(acc[r][1]);
        v[r][0] = p0.x + b1x; v[r][1] = p0.y + b1y;
        v[r][2] = p1.x + b1z; v[r][3] = p1.y + b1w;
        if (REL1) {
            int lr = ty * 4 + r;
            float rx = sRel[lr * 3], ry = sRel[lr * 3 + 1], rz = sRel[lr * 3 + 2];
            #pragma unroll
            for (int c = 0; c < 4; c++) {
                int col = tx * 4 + c;
                v[r][c] += rx * sWr1[col] + ry * sWr1[64 + col] + rz * sWr1[128 + col];
            }
        }
        #pragma unroll
        for (int c = 0; c < 4; c++) v[r][c] = fmaxf(v[r][c], 0.f);
        int row = row0 + ty * 4 + r;
        if (row < n) {
            size_t base = (size_t)row * 64 + tx * 4;
            if (NRES >= 1) {
                const float4 r1 = *reinterpret_cast<const float4*>(&res1[base]);
                v[r][0] += r1.x; v[r][1] += r1.y; v[r][2] += r1.z; v[r][3] += r1.w;
            }
            if (NRES >= 2) {
                const float4 r2 = *reinterpret_cast<const float4*>(&res2[base]);
                v[r][0] += r2.x; v[r][1] += r2.y; v[r][2] += r2.z; v[r][3] += r2.w;
            }
            if (STORE1) {
                float4 o = { v[r][0], v[r][1], v[r][2], v[r][3] };
                *reinterpret_cast<float4*>(&out1[base]) = o;
            }
        } else {
            v[r][0] = v[r][1] = v[r][2] = v[r][3] = 0.f;
        }
    }

    if (FUSE == 0) return;

    // ---- second GEMM: input = out1 tile (in registers v), staged in halves ----
    unsigned long long acc2[4][2];
    float accc[2];
    if (FUSE == 1) {
        #pragma unroll
        for (int r = 0; r < 4; r++) { acc2[r][0] = 0ULL; acc2[r][1] = 0ULL; }
    } else {
        accc[0] = b2[tid & 7]; accc[1] = accc[0];
    }

    #pragma unroll
    for (int half = 0; half < 2; half++) {
        __syncthreads();   // readers of sW / sAd done
        if (half == 0) {
            if (FUSE == 1) {
                for (int i = tid; i < 4096; i += 256) sW[i] = W2[i];
                if (REL2)
                    for (int i = tid; i < 192; i += 256) sWr2[i] = W2[4096 + i];
            } else {
                for (int i = tid; i < 512; i += 256) sW[i] = W2[i];
            }
        }
        // stage this half's columns (k = out1 col in [half*32, half*32+32))
        if ((tx >> 3) == half) {
            #pragma unroll
            for (int c = 0; c < 4; c++)
                #pragma unroll
                for (int r = 0; r < 4; r++)
                    sAd[(tx * 4 + c - half * 32) * 66 + (ty * 4 + r)] = make_float2(v[r][c], v[r][c]);
        }
        __syncthreads();
        if (FUSE == 1) {
            #pragma unroll 16
            for (int k = 0; k < 32; k++) {
                const ulonglong2 a01 = *reinterpret_cast<const ulonglong2*>(&sAd[k * 66 + ty * 4]);
                const ulonglong2 a23 = *reinterpret_cast<const ulonglong2*>(&sAd[k * 66 + ty * 4 + 2]);
                const ulonglong2 bv  = *reinterpret_cast<const ulonglong2*>(&sW[(half * 32 + k) * 64 + tx * 4]);
                ffma2(acc2[0][0], a01.x, bv.x); ffma2(acc2[0][1], a01.x, bv.y);
                ffma2(acc2[1][0], a01.y, bv.x); ffma2(acc2[1][1], a01.y, bv.y);
                ffma2(acc2[2][0], a23.x, bv.x); ffma2(acc2[2][1], a23.x, bv.y);
                ffma2(acc2[3][0], a23.y, bv.x); ffma2(acc2[3][1], a23.y, bv.y);
            }
        } else {
            int r8 = tid >> 3, cls = tid & 7;
            #pragma unroll
            for (int h = 0; h < 2; h++) {
                int lr = (h == 0) ? r8 : (r8 + 32);
                float a = accc[h];
                #pragma unroll 16
                for (int k = 0; k < 32; k++)
                    a = fmaf(sAd[k * 66 + lr].x, sW[(half * 32 + k) * 8 + cls], a);
                accc[h] = a;
            }
        }
    }

    if (FUSE == 1) {
        const float b2x = b2[tx * 4], b2y = b2[tx * 4 + 1], b2z = b2[tx * 4 + 2], b2w = b2[tx * 4 + 3];
        #pragma unroll
        for (int r = 0; r < 4; r++) {
            int row = row0 + ty * 4 + r;
            if (row >= n) continue;
            float2 p0 = up2(acc2[r][0]), p1 = up2(acc2[r][1]);
            float w0 = p0.x + b2x, w1 = p0.y + b2y, w2 = p1.x + b2z, w3 = p1.y + b2w;
            if (REL2) {
                int lr = ty * 4 + r;
                float rx = sRel[lr * 3], ry = sRel[lr * 3 + 1], rz = sRel[lr * 3 + 2];
                int col = tx * 4;
                w0 += rx * sWr2[col]     + ry * sWr2[64 + col]     + rz * sWr2[128 + col];
                w1 += rx * sWr2[col + 1] + ry * sWr2[64 + col + 1] + rz * sWr2[128 + col + 1];
                w2 += rx * sWr2[col + 2] + ry * sWr2[64 + col + 2] + rz * sWr2[128 + col + 2];
                w3 += rx * sWr2[col + 3] + ry * sWr2[64 + col + 3] + rz * sWr2[128 + col + 3];
            }
            if (RELU2) {
                w0 = fmaxf(w0, 0.f); w1 = fmaxf(w1, 0.f);
                w2 = fmaxf(w2, 0.f); w3 = fmaxf(w3, 0.f);
            }
            float4 o = { w0, w1, w2, w3 };
            *reinterpret_cast<float4*>(&out2[(size_t)row * 64 + tx * 4]) = o;
        }
    } else {
        int r8 = tid >> 3, cls = tid & 7;
        #pragma unroll
        for (int h = 0; h < 2; h++) {
            int row = row0 + ((h == 0) ? r8 : (r8 + 32));
            if (row < n) out2[(size_t)row * 8 + cls] = accc[h];
        }
    }
}

// ---------------- host orchestration ----------------
constexpr int GEMM_SMEM = 32 * 66 * (int)sizeof(float2);   // 16896 dynamic

extern "C" void kernel_launch(void* const* d_in, const int* in_sizes, int n_in,
                              void* d_out, int out_size) {
    (void)in_sizes; (void)n_in; (void)out_size;
    float* A = nullptr;
    cudaGetSymbolAddress((void**)&A, g_arena);

    float* f1   = A + OFF_F1;
    float* f2   = A + OFF_F2;
    float* f21  = A + OFF_F21;
    float* f5   = A + OFF_F5;
    float* f6   = A + OFF_F6;
    float* np   = A + OFF_NP;
    float* agg  = A + OFF_AGG;
    float* rel  = A + OFF_REL;
    float* mA   = A + OFF_MA;
    float* mB   = A + OFF_MB;
    float* mnp  = A + OFF_MNP;
    float* magg = A + OFF_MAGG;
    int* cnt0  = (int*)(A + OFF_CNT0);
    int* cnt1  = (int*)(A + OFF_CNT1);
    int* cntL  = (int*)(A + OFF_CNTL);
    int* offs0 = (int*)(A + OFF_OFFS0);
    int* cur0  = (int*)(A + OFF_CUR0);
    int* csr0  = (int*)(A + OFF_CSR0);
    int* offs1 = (int*)(A + OFF_OFFS1);
    int* cur1  = (int*)(A + OFF_CUR1);
    int* csr1  = (int*)(A + OFF_CSR1);
    int* offsL = (int*)(A + OFF_OFFSL);
    int* curL  = (int*)(A + OFF_CURL);
    int* csrL  = (int*)(A + OFF_CSRL);

    const float* features = (const float*)d_in[0];
    const float* points   = (const float*)d_in[1];
    const float* centers  = (const float*)d_in[2];
    const int*   l0       = (const int*)d_in[3];
    const int*   l1       = (const int*)d_in[4];
    const int*   labels   = (const int*)d_in[5];
    const float* W_fe     = (const float*)d_in[6];
    const float* b_fe     = (const float*)d_in[7];
    const float* mini_We  = (const float*)d_in[8];
    const float* mini_be  = (const float*)d_in[9];
    const float* mini_Wu  = (const float*)d_in[10];
    const float* mini_bu  = (const float*)d_in[11];
    const float* W_m1     = (const float*)d_in[12];
    const float* b_m1     = (const float*)d_in[13];
    const float* W_m2     = (const float*)d_in[14];
    const float* b_m2     = (const float*)d_in[15];
    const float* gnn_We   = (const float*)d_in[16];
    const float* gnn_be   = (const float*)d_in[17];
    const float* gnn_Wu   = (const float*)d_in[18];
    const float* gnn_bu   = (const float*)d_in[19];
    const float* W_l      = (const float*)d_in[20];
    const float* b_l      = (const float*)d_in[21];
    const float* W_c      = (const float*)d_in[22];
    const float* b_c      = (const float*)d_in[23];
    float* out = (float*)d_out;

    const int TN = (Nn + 63) / 64;   // 1563
    const int TM = (Mm + 63) / 64;   // 196

    const float* We0 = mini_We;               const float* be0 = mini_be;
    const float* We1 = mini_We + 67 * 64;     const float* be1 = mini_be + 64;
    const float* We2 = mini_We + 2 * 67 * 64; const float* be2 = mini_be + 128;
    const float* We3 = mini_We + 3 * 67 * 64; const float* be3 = mini_be + 192;
    const float* Wu0 = mini_Wu;               const float* bu0 = mini_bu;
    const float* Wu1 = mini_Wu + 4096;        const float* bu1 = mini_bu + 64;
    const float* Wu2 = mini_Wu + 2 * 4096;    const float* bu2 = mini_bu + 128;
    const float* Wu3 = mini_Wu + 3 * 4096;    const float* bu3 = mini_bu + 192;
    const float* gWe0 = gnn_We;               const float* gbe0 = gnn_be;
    const float* gWe1 = gnn_We + 67 * 64;     const float* gbe1 = gnn_be + 64;
    const float* gWu0 = gnn_Wu;               const float* gbu0 = gnn_bu;
    const float* gWu1 = gnn_Wu + 4096;        const float* gbu1 = gnn_bu + 64;

    // ---- CSR builds (edges by dst, points by label) ----
    cudaMemsetAsync((void*)cnt0, 0, (OFF_OFFS0 - OFF_CNT0) * sizeof(float));
    k_hist<<<(E0n + 255) / 256, 256>>>((const int2*)l0, cnt0, E0n);
    k_hist<<<(E1n + 255) / 256, 256>>>((const int2*)l1, cnt1, E1n);
    k_histL<<<(Nn + 255) / 256, 256>>>(labels, cntL, Nn);
    k_scan3<<<3, 1024>>>(cnt0, offs0, cur0, Nn, cnt1, offs1, cur1, Mm, cntL, offsL, curL, Mm);
    k_scatter<<<(E0n + 255) / 256, 256>>>((const int2*)l0, cur0, csr0, E0n);
    k_scatter<<<(E1n + 255) / 256, 256>>>((const int2*)l1, cur1, csr1, E1n);
    k_scatterL<<<(Nn + 255) / 256, 256>>>(labels, curL, csrL, Nn);

    // ---- f1 = relu([feat,rel]@W_fe+b) ; np0 = f1@We0_feat+be0 (fused) ----
    k_gemm<4, false, true, true, 0, true, 1, false, false><<<TN, 256, GEMM_SMEM>>>(
        features, nullptr, points, centers, labels, rel,
        W_fe, b_fe, nullptr, nullptr, f1, We0 + 192, be0, np, Nn);

    // ---- GNN layer 0 on N ----
    k_agg<<<(Nn + 7) / 8, 256>>>(offs0, csr0, points, (const float2*)np, We0, (float2*)agg, Nn);
    k_gemm<64, false, false, false, 1, true, 1, false, false><<<TN, 256, GEMM_SMEM>>>(
        agg, nullptr, nullptr, nullptr, nullptr, rel,
        Wu0, bu0, f1, nullptr, f2, We1 + 192, be1, np, Nn);   // f2 ; np1

    // ---- GNN layer 1 on N, fused with h = relu([f21,rel]@W_m1+b_m1) ----
    k_agg<<<(Nn + 7) / 8, 256>>>(offs0, csr0, points, (const float2*)np, We1, (float2*)agg, Nn);
    k_gemm<64, false, false, false, 1, true, 1, true, true><<<TN, 256, GEMM_SMEM>>>(
        agg, nullptr, nullptr, nullptr, nullptr, rel,
        Wu1, bu1, f2, nullptr, f21, W_m1, b_m1, np, Nn);      // f21 ; h -> np

    // ---- cluster branch ----
    k_segsum<<<(Mm + 7) / 8, 256>>>(offsL, csrL, (const float2*)np, (float2*)mA, Mm);
    k_gemm<64, false, false, false, 0, true, 1, false, false><<<TM, 256, GEMM_SMEM>>>(
        mA, nullptr, nullptr, nullptr, nullptr, rel,
        W_m2, b_m2, nullptr, nullptr, mB, gWe0 + 192, gbe0, mnp, Mm);   // f3=mB ; npM0
    k_agg<<<(Mm + 7) / 8, 256>>>(offs1, csr1, centers, (const float2*)mnp, gWe0, (float2*)magg, Mm);
    k_gemm<64, false, false, false, 1, true, 1, false, false><<<TM, 256, GEMM_SMEM>>>(
        magg, nullptr, nullptr, nullptr, nullptr, rel,
        gWu0, gbu0, mB, nullptr, mA, gWe1 + 192, gbe1, mnp, Mm);        // f4=mA ; npM1
    k_agg<<<(Mm + 7) / 8, 256>>>(offs1, csr1, centers, (const float2*)mnp, gWe1, (float2*)magg, Mm);
    k_gemm<64, false, false, false, 1, true, 0, false, false><<<TM, 256, GEMM_SMEM>>>(
        magg, nullptr, nullptr, nullptr, nullptr, rel,
        gWu1, gbu1, mA, nullptr, mB, nullptr, nullptr, nullptr, Mm);    // f4_1=mB

    // ---- f5 = relu([f4_1[labels], rel]@W_l+b_l) ; np2 fused ----
    k_gemm<64, true, false, true, 0, true, 1, false, false><<<TN, 256, GEMM_SMEM>>>(
        mB, labels, nullptr, nullptr, nullptr, rel,
        W_l, b_l, nullptr, nullptr, f5, We2 + 192, be2, np, Nn);

    // ---- GNN layer 2 on N: f6 = relu(agg@Wu2+bu2)+f5+f21 ; np3 fused ----
    k_agg<<<(Nn + 7) / 8, 256>>>(offs0, csr0, points, (const float2*)np, We2, (float2*)agg, Nn);
    k_gemm<64, false, false, false, 2, true, 1, false, false><<<TN, 256, GEMM_SMEM>>>(
        agg, nullptr, nullptr, nullptr, nullptr, rel,
        Wu2, bu2, f5, f21, f6, We3 + 192, be3, np, Nn);

    // ---- GNN layer 3 on N fused with classifier ----
    k_agg<<<(Nn + 7) / 8, 256>>>(offs0, csr0, points, (const float2*)np, We3, (float2*)agg, Nn);
    k_gemm<64, false, false, false, 2, false, 2, false, false><<<TN, 256, GEMM_SMEM>>>(
        agg, nullptr, nullptr, nullptr, nullptr, rel,
        Wu3, bu3, f6, f2, nullptr, W_c, b_c, out, Nn);
}

// round 4
// speedup vs baseline: 1.2135x; 1.1678x over previous
#include <cuda_runtime.h>
#include <cstddef>
#include <cstdint>

// ---------------- problem constants ----------------
constexpr int Nn  = 100000;
constexpr int Mm  = 12500;
constexpr int E0n = 1600000;
constexpr int E1n = 400000;

constexpr int NB0 = (Nn + 1023) / 1024;   // 98
constexpr int NB1 = (Mm + 1023) / 1024;   // 13
constexpr int NBL = (Mm + 1023) / 1024;   // 13
constexpr int TOTB = NB0 + NB1 + NBL;     // 124

constexpr size_t F_N64 = (size_t)Nn * 64;
constexpr size_t F_M64 = (size_t)Mm * 64;
constexpr size_t pad16(size_t x) { return (x + 15) & ~(size_t)15; }

// arena (floats)
constexpr size_t OFF_F1   = 0;
constexpr size_t OFF_F2   = OFF_F1  + F_N64;
constexpr size_t OFF_F21  = OFF_F2  + F_N64;
constexpr size_t OFF_F5   = OFF_F21 + F_N64;
constexpr size_t OFF_F6   = OFF_F5  + F_N64;
constexpr size_t OFF_NP   = OFF_F6  + F_N64;
constexpr size_t OFF_AGG  = OFF_NP  + F_N64;
constexpr size_t OFF_REL  = OFF_AGG + F_N64;
constexpr size_t OFF_MA   = OFF_REL + pad16((size_t)Nn * 3);
constexpr size_t OFF_MB   = OFF_MA  + F_M64;
constexpr size_t OFF_MNP  = OFF_MB  + F_M64;
constexpr size_t OFF_MAGG = OFF_MNP + F_M64;
// int region
constexpr size_t OFF_CNT0  = OFF_MAGG + F_M64;
constexpr size_t OFF_CNT1  = OFF_CNT0  + pad16(Nn);
constexpr size_t OFF_CNTL  = OFF_CNT1  + pad16(Mm);
constexpr size_t OFF_OFFS0 = OFF_CNTL  + pad16(Mm);
constexpr size_t OFF_CUR0  = OFF_OFFS0 + pad16(Nn + 1);
constexpr size_t OFF_CSR0  = OFF_CUR0  + pad16(Nn);
constexpr size_t OFF_OFFS1 = OFF_CSR0  + pad16(E0n);
constexpr size_t OFF_CUR1  = OFF_OFFS1 + pad16(Mm + 1);
constexpr size_t OFF_CSR1  = OFF_CUR1  + pad16(Mm);
constexpr size_t OFF_OFFSL = OFF_CSR1  + pad16(E1n);
constexpr size_t OFF_CURL  = OFF_OFFSL + pad16(Mm + 1);
constexpr size_t OFF_CSRL  = OFF_CURL  + pad16(Mm);
constexpr size_t OFF_BSUM  = OFF_CSRL  + pad16(Nn);
constexpr size_t ARENA_SZ  = OFF_BSUM  + pad16(TOTB);

__device__ __align__(256) static float g_arena[ARENA_SZ];

// ---------------- helpers ----------------
__device__ __forceinline__ void ffma2(unsigned long long& d, unsigned long long a, unsigned long long b) {
    asm("fma.rn.f32x2 %0, %1, %2, %0;" : "+l"(d) : "l"(a), "l"(b));
}
__device__ __forceinline__ float2 up2(unsigned long long x) {
    float2 f;
    asm("mov.b64 {%0, %1}, %2;" : "=f"(f.x), "=f"(f.y) : "l"(x));
    return f;
}

// ---------------- CSR build ----------------
__global__ void k_hist(const int2* __restrict__ edges, int* __restrict__ cnt, int E) {
    int e = blockIdx.x * blockDim.x + threadIdx.x;
    if (e < E) atomicAdd(&cnt[edges[e].y], 1);
}
__global__ void k_histL(const int* __restrict__ lab, int* __restrict__ cnt, int n) {
    int i = blockIdx.x * blockDim.x + threadIdx.x;
    if (i < n) atomicAdd(&cnt[lab[i]], 1);
}

// Pass A: per-block scan of 1024-element tiles of the 3 count arrays.
__global__ void k_scanA(const int* __restrict__ c0, int* __restrict__ o0,
                        const int* __restrict__ c1, int* __restrict__ o1,
                        const int* __restrict__ c2, int* __restrict__ o2,
                        int* __restrict__ bsum) {
    const int b = blockIdx.x;
    const int* cnt; int* offs; int n; int lb;
    if (b < NB0)            { cnt = c0; offs = o0; n = Nn; lb = b; }
    else if (b < NB0 + NB1) { cnt = c1; offs = o1; n = Mm; lb = b - NB0; }
    else                    { cnt = c2; offs = o2; n = Mm; lb = b - NB0 - NB1; }
    __shared__ int s[1024];
    int t = threadIdx.x;
    int g = lb * 1024 + t;
    int v = (g < n) ? cnt[g] : 0;
    s[t] = v;
    __syncthreads();
    #pragma unroll
    for (int off = 1; off < 1024; off <<= 1) {
        int u = (t >= off) ? s[t - off] : 0;
        __syncthreads();
        s[t] += u;
        __syncthreads();
    }
    if (g < n) offs[g] = s[t] - v;          // exclusive within block
    if (t == 1023) bsum[b] = s[1023];       // block total
}

// Pass B: 1 block, warp per segment — exclusive-scan block sums in place, total -> offs[n].
__global__ void k_scanB(int* __restrict__ bsum, int* __restrict__ o0,
                        int* __restrict__ o1, int* __restrict__ o2) {
    int w = threadIdx.x >> 5, lane = threadIdx.x & 31;
    int base, nb; int* offs; int n;
    if (w == 0)      { base = 0;         nb = NB0; offs = o0; n = Nn; }
    else if (w == 1) { base = NB0;       nb = NB1; offs = o1; n = Mm; }
    else             { base = NB0 + NB1; nb = NBL; offs = o2; n = Mm; }
    int carry = 0;
    for (int i0 = 0; i0 < nb; i0 += 32) {
        int i = i0 + lane;
        int orig = (i < nb) ? bsum[base + i] : 0;
        int v = orig;
        #pragma unroll
        for (int d = 1; d < 32; d <<= 1) {
            int u = __shfl_up_sync(0xffffffffu, v, d);
            if (lane >= d) v += u;
        }
        if (i < nb) bsum[base + i] = carry + v - orig;   // exclusive
        carry += __shfl_sync(0xffffffffu, v, 31);
    }
    if (lane == 0) offs[n] = carry;
}

// Pass C: add block offsets, write offs and cur (coalesced).
__global__ void k_scanC(int* __restrict__ o0, int* __restrict__ u0,
                        int* __restrict__ o1, int* __restrict__ u1,
                        int* __restrict__ o2, int* __restrict__ u2,
                        const int* __restrict__ bsum) {
    const int b = blockIdx.x;
    int* offs; int* cur; int n; int lb;
    if (b < NB0)            { offs = o0; cur = u0; n = Nn; lb = b; }
    else if (b < NB0 + NB1) { offs = o1; cur = u1; n = Mm; lb = b - NB0; }
    else                    { offs = o2; cur = u2; n = Mm; lb = b - NB0 - NB1; }
    int g = lb * 1024 + threadIdx.x;
    if (g < n) {
        int val = offs[g] + bsum[b];
        offs[g] = val;
        cur[g]  = val;
    }
}

__global__ void k_scatter(const int2* __restrict__ edges, int* __restrict__ cur,
                          int* __restrict__ csrc, int E) {
    int e = blockIdx.x * blockDim.x + threadIdx.x;
    if (e < E) {
        int2 ed = edges[e];
        int p = atomicAdd(&cur[ed.y], 1);
        csrc[p] = ed.x;
    }
}
__global__ void k_scatterL(const int* __restrict__ lab, int* __restrict__ cur,
                           int* __restrict__ idx, int n) {
    int i = blockIdx.x * blockDim.x + threadIdx.x;
    if (i < n) {
        int p = atomicAdd(&cur[lab[i]], 1);
        idx[p] = i;
    }
}

// ---------------- edge aggregation (CSR max, fused positional part) ----------------
__global__ void k_agg(const int* __restrict__ offs, const int* __restrict__ csrc,
                      const float* __restrict__ pos, const float2* __restrict__ np2,
                      const float* __restrict__ Wp, float2* __restrict__ agg, int n) {
    int lane = threadIdx.x & 31;
    int d = (blockIdx.x * blockDim.x + threadIdx.x) >> 5;
    if (d >= n) return;
    int c0 = 2 * lane, c1 = c0 + 1;
    float w0x = Wp[c0],       w0y = Wp[c1];
    float w1x = Wp[64 + c0],  w1y = Wp[64 + c1];
    float w2x = Wp[128 + c0], w2y = Wp[128 + c1];
    int s0 = offs[d], s1 = offs[d + 1];
    float px = pos[3 * d], py = pos[3 * d + 1], pz = pos[3 * d + 2];
    float ax = 0.f, ay = 0.f;
    int s = (s0 < s1) ? csrc[s0] : 0;
    for (int e = s0; e < s1; e++) {
        int sn = (e + 1 < s1) ? csrc[e + 1] : 0;
        float dx = pos[3 * s]     - px;
        float dy = pos[3 * s + 1] - py;
        float dz = pos[3 * s + 2] - pz;
        float2 v = np2[(size_t)s * 32 + lane];
        float pa = fmaf(dx, w0x, fmaf(dy, w1x, dz * w2x));
        float pb = fmaf(dx, w0y, fmaf(dy, w1y, dz * w2y));
        ax = fmaxf(ax, v.x + pa);
        ay = fmaxf(ay, v.y + pb);
        s = sn;
    }
    agg[(size_t)d * 32 + lane] = make_float2(ax, ay);
}

// segment sum via label-CSR: warp per cluster
__global__ void k_segsum(const int* __restrict__ offs, const int* __restrict__ idx,
                         const float2* __restrict__ h, float2* __restrict__ c, int m) {
    int lane = threadIdx.x & 31;
    int d = (blockIdx.x * blockDim.x + threadIdx.x) >> 5;
    if (d >= m) return;
    int s0 = offs[d], s1 = offs[d + 1];
    float sx = 0.f, sy = 0.f;
    for (int e = s0; e < s1; e++) {
        int p = idx[e];
        float2 v = h[(size_t)p * 32 + lane];
        sx += v.x; sy += v.y;
    }
    c[(size_t)d * 32 + lane] = make_float2(sx, sy);
}

// ---------------- unified GEMM kernel ----------------
// out1 = relu(A @ W1[0:K1] + b1 (+ rel @ W1[K1:K1+3])) (+res1)(+res2)
// FUSE==1: out2 = [out1 (,rel)] @ W2 + b2 (optional relu2)
// FUSE==2: out2 = out1 @ W2(64x8) + b2  (classifier)
template<int K1, bool GATHER, bool MAKEREL, bool REL1, int NRES, bool STORE1,
         int FUSE, bool REL2, bool RELU2>
__global__ __launch_bounds__(256)
void k_gemm(const float* __restrict__ in, const int* __restrict__ gidx,
            const float* __restrict__ points, const float* __restrict__ centers,
            const int* __restrict__ labels, float* __restrict__ relg,
            const float* __restrict__ W1, const float* __restrict__ b1,
            const float* __restrict__ res1, const float* __restrict__ res2,
            float* __restrict__ out1,
            const float* __restrict__ W2, const float* __restrict__ b2,
            float* __restrict__ out2, int n) {
    extern __shared__ float2 sAd[];          // [KC][66] duplicated A: {a,a}  (KC<=32)
    __shared__ float sW[64 * 64];
    __shared__ float sWr1[192];
    __shared__ float sWr2[192];
    __shared__ float sRel[192];

    constexpr int KC = (K1 < 32) ? K1 : 32;

    const int tid = threadIdx.x;
    const int row0 = blockIdx.x * 64;

    for (int i = tid; i < K1 * 64; i += 256) sW[i] = W1[i];
    if (REL1)
        for (int i = tid; i < 192; i += 256) sWr1[i] = W1[K1 * 64 + i];
    if (MAKEREL) {
        if (tid < 64) {
            int row = row0 + tid;
            float rx = 0.f, ry = 0.f, rz = 0.f;
            if (row < n) {
                int l = labels[row];
                rx = points[3 * row]     - centers[3 * l];
                ry = points[3 * row + 1] - centers[3 * l + 1];
                rz = points[3 * row + 2] - centers[3 * l + 2];
                relg[3 * row] = rx; relg[3 * row + 1] = ry; relg[3 * row + 2] = rz;
            }
            sRel[tid * 3] = rx; sRel[tid * 3 + 1] = ry; sRel[tid * 3 + 2] = rz;
        }
    } else if (REL1 || REL2) {
        if (tid < 64) {
            int row = row0 + tid;
            float rx = 0.f, ry = 0.f, rz = 0.f;
            if (row < n) { rx = relg[3 * row]; ry = relg[3 * row + 1]; rz = relg[3 * row + 2]; }
            sRel[tid * 3] = rx; sRel[tid * 3 + 1] = ry; sRel[tid * 3 + 2] = rz;
        }
    }

    const int tx = tid & 15, ty = tid >> 4;
    unsigned long long acc[4][2];
    #pragma unroll
    for (int r = 0; r < 4; r++) { acc[r][0] = 0ULL; acc[r][1] = 0ULL; }

    // ---- first GEMM, A chunked over K ----
    for (int kc = 0; kc < K1; kc += KC) {
        __syncthreads();
        for (int i = tid; i < KC * 64; i += 256) {
            int r = i / KC, k = i - r * KC;
            int row = row0 + r;
            float v = 0.f;
            if (row < n) {
                int sr = GATHER ? gidx[row] : row;
                v = in[(size_t)sr * K1 + kc + k];
            }
            sAd[k * 66 + r] = make_float2(v, v);
        }
        __syncthreads();
        #pragma unroll 16
        for (int k = 0; k < KC; k++) {
            const ulonglong2 a01 = *reinterpret_cast<const ulonglong2*>(&sAd[k * 66 + ty * 4]);
            const ulonglong2 a23 = *reinterpret_cast<const ulonglong2*>(&sAd[k * 66 + ty * 4 + 2]);
            const ulonglong2 bv  = *reinterpret_cast<const ulonglong2*>(&sW[(kc + k) * 64 + tx * 4]);
            ffma2(acc[0][0], a01.x, bv.x); ffma2(acc[0][1], a01.x, bv.y);
            ffma2(acc[1][0], a01.y, bv.x); ffma2(acc[1][1], a01.y, bv.y);
            ffma2(acc[2][0], a23.x, bv.x); ffma2(acc[2][1], a23.x, bv.y);
            ffma2(acc[3][0], a23.y, bv.x); ffma2(acc[3][1], a23.y, bv.y);
        }
    }

    // ---- epilogue 1 ----
    float v[4][4];
    const float b1x = b1[tx * 4], b1y = b1[tx * 4 + 1], b1z = b1[tx * 4 + 2], b1w = b1[tx * 4 + 3];
    #pragma unroll
    for (int r = 0; r < 4; r++) {
        float2 p0 = up2(acc[r][0]), p1 = up2(acc[r][1]);
        v[r][0] = p0.x + b1x; v[r][1] = p0.y + b1y;
        v[r][2] = p1.x + b1z; v[r][3] = p1.y + b1w;
        if (REL1) {
            int lr = ty * 4 + r;
            float rx = sRel[lr * 3], ry = sRel[lr * 3 + 1], rz = sRel[lr * 3 + 2];
            #pragma unroll
            for (int c = 0; c < 4; c++) {
                int col = tx * 4 + c;
                v[r][c] += rx * sWr1[col] + ry * sWr1[64 + col] + rz * sWr1[128 + col];
            }
        }
        #pragma unroll
        for (int c = 0; c < 4; c++) v[r][c] = fmaxf(v[r][c], 0.f);
        int row = row0 + ty * 4 + r;
        if (row < n) {
            size_t base = (size_t)row * 64 + tx * 4;
            if (NRES >= 1) {
                const float4 r1 = *reinterpret_cast<const float4*>(&res1[base]);
                v[r][0] += r1.x; v[r][1] += r1.y; v[r][2] += r1.z; v[r][3] += r1.w;
            }
            if (NRES >= 2) {
                const float4 r2 = *reinterpret_cast<const float4*>(&res2[base]);
                v[r][0] += r2.x; v[r][1] += r2.y; v[r][2] += r2.z; v[r][3] += r2.w;
            }
            if (STORE1) {
                float4 o = { v[r][0], v[r][1], v[r][2], v[r][3] };
                *reinterpret_cast<float4*>(&out1[base]) = o;
            }
        } else {
            v[r][0] = v[r][1] = v[r][2] = v[r][3] = 0.f;
        }
    }

    if (FUSE == 0) return;

    // ---- second GEMM: input = out1 tile (registers v), staged in halves ----
    unsigned long long acc2[4][2];
    float accc[2];
    if (FUSE == 1) {
        #pragma unroll
        for (int r = 0; r < 4; r++) { acc2[r][0] = 0ULL; acc2[r][1] = 0ULL; }
    } else {
        accc[0] = b2[tid & 7]; accc[1] = accc[0];
    }

    #pragma unroll
    for (int half = 0; half < 2; half++) {
        __syncthreads();
        if (half == 0) {
            if (FUSE == 1) {
                for (int i = tid; i < 4096; i += 256) sW[i] = W2[i];
                if (REL2)
                    for (int i = tid; i < 192; i += 256) sWr2[i] = W2[4096 + i];
            } else {
                for (int i = tid; i < 512; i += 256) sW[i] = W2[i];
            }
        }
        if ((tx >> 3) == half) {
            #pragma unroll
            for (int c = 0; c < 4; c++)
                #pragma unroll
                for (int r = 0; r < 4; r++)
                    sAd[(tx * 4 + c - half * 32) * 66 + (ty * 4 + r)] = make_float2(v[r][c], v[r][c]);
        }
        __syncthreads();
        if (FUSE == 1) {
            #pragma unroll 16
            for (int k = 0; k < 32; k++) {
                const ulonglong2 a01 = *reinterpret_cast<const ulonglong2*>(&sAd[k * 66 + ty * 4]);
                const ulonglong2 a23 = *reinterpret_cast<const ulonglong2*>(&sAd[k * 66 + ty * 4 + 2]);
                const ulonglong2 bv  = *reinterpret_cast<const ulonglong2*>(&sW[(half * 32 + k) * 64 + tx * 4]);
                ffma2(acc2[0][0], a01.x, bv.x); ffma2(acc2[0][1], a01.x, bv.y);
                ffma2(acc2[1][0], a01.y, bv.x); ffma2(acc2[1][1], a01.y, bv.y);
                ffma2(acc2[2][0], a23.x, bv.x); ffma2(acc2[2][1], a23.x, bv.y);
                ffma2(acc2[3][0], a23.y, bv.x); ffma2(acc2[3][1], a23.y, bv.y);
            }
        } else {
            int r8 = tid >> 3, cls = tid & 7;
            #pragma unroll
            for (int h = 0; h < 2; h++) {
                int lr = (h == 0) ? r8 : (r8 + 32);
                float a = accc[h];
                #pragma unroll 16
                for (int k = 0; k < 32; k++)
                    a = fmaf(sAd[k * 66 + lr].x, sW[(half * 32 + k) * 8 + cls], a);
                accc[h] = a;
            }
        }
    }

    if (FUSE == 1) {
        const float b2x = b2[tx * 4], b2y = b2[tx * 4 + 1], b2z = b2[tx * 4 + 2], b2w = b2[tx * 4 + 3];
        #pragma unroll
        for (int r = 0; r < 4; r++) {
            int row = row0 + ty * 4 + r;
            if (row >= n) continue;
            float2 p0 = up2(acc2[r][0]), p1 = up2(acc2[r][1]);
            float w0 = p0.x + b2x, w1 = p0.y + b2y, w2 = p1.x + b2z, w3 = p1.y + b2w;
            if (REL2) {
                int lr = ty * 4 + r;
                float rx = sRel[lr * 3], ry = sRel[lr * 3 + 1], rz = sRel[lr * 3 + 2];
                int col = tx * 4;
                w0 += rx * sWr2[col]     + ry * sWr2[64 + col]     + rz * sWr2[128 + col];
                w1 += rx * sWr2[col + 1] + ry * sWr2[64 + col + 1] + rz * sWr2[128 + col + 1];
                w2 += rx * sWr2[col + 2] + ry * sWr2[64 + col + 2] + rz * sWr2[128 + col + 2];
                w3 += rx * sWr2[col + 3] + ry * sWr2[64 + col + 3] + rz * sWr2[128 + col + 3];
            }
            if (RELU2) {
                w0 = fmaxf(w0, 0.f); w1 = fmaxf(w1, 0.f);
                w2 = fmaxf(w2, 0.f); w3 = fmaxf(w3, 0.f);
            }
            float4 o = { w0, w1, w2, w3 };
            *reinterpret_cast<float4*>(&out2[(size_t)row * 64 + tx * 4]) = o;
        }
    } else {
        int r8 = tid >> 3, cls = tid & 7;
        #pragma unroll
        for (int h = 0; h < 2; h++) {
            int row = row0 + ((h == 0) ? r8 : (r8 + 32));
            if (row < n) out2[(size_t)row * 8 + cls] = accc[h];
        }
    }
}

// ---------------- host orchestration ----------------
constexpr int GEMM_SMEM = 32 * 66 * (int)sizeof(float2);   // 16896 dynamic

extern "C" void kernel_launch(void* const* d_in, const int* in_sizes, int n_in,
                              void* d_out, int out_size) {
    (void)in_sizes; (void)n_in; (void)out_size;
    float* A = nullptr;
    cudaGetSymbolAddress((void**)&A, g_arena);

    float* f1   = A + OFF_F1;
    float* f2   = A + OFF_F2;
    float* f21  = A + OFF_F21;
    float* f5   = A + OFF_F5;
    float* f6   = A + OFF_F6;
    float* np   = A + OFF_NP;
    float* agg  = A + OFF_AGG;
    float* rel  = A + OFF_REL;
    float* mA   = A + OFF_MA;
    float* mB   = A + OFF_MB;
    float* mnp  = A + OFF_MNP;
    float* magg = A + OFF_MAGG;
    int* cnt0  = (int*)(A + OFF_CNT0);
    int* cnt1  = (int*)(A + OFF_CNT1);
    int* cntL  = (int*)(A + OFF_CNTL);
    int* offs0 = (int*)(A + OFF_OFFS0);
    int* cur0  = (int*)(A + OFF_CUR0);
    int* csr0  = (int*)(A + OFF_CSR0);
    int* offs1 = (int*)(A + OFF_OFFS1);
    int* cur1  = (int*)(A + OFF_CUR1);
    int* csr1  = (int*)(A + OFF_CSR1);
    int* offsL = (int*)(A + OFF_OFFSL);
    int* curL  = (int*)(A + OFF_CURL);
    int* csrL  = (int*)(A + OFF_CSRL);
    int* bsum  = (int*)(A + OFF_BSUM);

    const float* features = (const float*)d_in[0];
    const float* points   = (const float*)d_in[1];
    const float* centers  = (const float*)d_in[2];
    const int*   l0       = (const int*)d_in[3];
    const int*   l1       = (const int*)d_in[4];
    const int*   labels   = (const int*)d_in[5];
    const float* W_fe     = (const float*)d_in[6];
    const float* b_fe     = (const float*)d_in[7];
    const float* mini_We  = (const float*)d_in[8];
    const float* mini_be  = (const float*)d_in[9];
    const float* mini_Wu  = (const float*)d_in[10];
    const float* mini_bu  = (const float*)d_in[11];
    const float* W_m1     = (const float*)d_in[12];
    const float* b_m1     = (const float*)d_in[13];
    const float* W_m2     = (const float*)d_in[14];
    const float* b_m2     = (const float*)d_in[15];
    const float* gnn_We   = (const float*)d_in[16];
    const float* gnn_be   = (const float*)d_in[17];
    const float* gnn_Wu   = (const float*)d_in[18];
    const float* gnn_bu   = (const float*)d_in[19];
    const float* W_l      = (const float*)d_in[20];
    const float* b_l      = (const float*)d_in[21];
    const float* W_c      = (const float*)d_in[22];
    const float* b_c      = (const float*)d_in[23];
    float* out = (float*)d_out;

    const int TN = (Nn + 63) / 64;   // 1563
    const int TM = (Mm + 63) / 64;   // 196

    const float* We0 = mini_We;               const float* be0 = mini_be;
    const float* We1 = mini_We + 67 * 64;     const float* be1 = mini_be + 64;
    const float* We2 = mini_We + 2 * 67 * 64; const float* be2 = mini_be + 128;
    const float* We3 = mini_We + 3 * 67 * 64; const float* be3 = mini_be + 192;
    const float* Wu0 = mini_Wu;               const float* bu0 = mini_bu;
    const float* Wu1 = mini_Wu + 4096;        const float* bu1 = mini_bu + 64;
    const float* Wu2 = mini_Wu + 2 * 4096;    const float* bu2 = mini_bu + 128;
    const float* Wu3 = mini_Wu + 3 * 4096;    const float* bu3 = mini_bu + 192;
    const float* gWe0 = gnn_We;               const float* gbe0 = gnn_be;
    const float* gWe1 = gnn_We + 67 * 64;     const float* gbe1 = gnn_be + 64;
    const float* gWu0 = gnn_Wu;               const float* gbu0 = gnn_bu;
    const float* gWu1 = gnn_Wu + 4096;        const float* gbu1 = gnn_bu + 64;

    // ---- CSR builds (edges by dst, points by label) ----
    cudaMemsetAsync((void*)cnt0, 0, (OFF_OFFS0 - OFF_CNT0) * sizeof(float));
    k_hist<<<(E0n + 255) / 256, 256>>>((const int2*)l0, cnt0, E0n);
    k_hist<<<(E1n + 255) / 256, 256>>>((const int2*)l1, cnt1, E1n);
    k_histL<<<(Nn + 255) / 256, 256>>>(labels, cntL, Nn);
    k_scanA<<<TOTB, 1024>>>(cnt0, offs0, cnt1, offs1, cntL, offsL, bsum);
    k_scanB<<<1, 96>>>(bsum, offs0, offs1, offsL);
    k_scanC<<<TOTB, 1024>>>(offs0, cur0, offs1, cur1, offsL, curL, bsum);
    k_scatter<<<(E0n + 255) / 256, 256>>>((const int2*)l0, cur0, csr0, E0n);
    k_scatter<<<(E1n + 255) / 256, 256>>>((const int2*)l1, cur1, csr1, E1n);
    k_scatterL<<<(Nn + 255) / 256, 256>>>(labels, curL, csrL, Nn);

    // ---- f1 = relu([feat,rel]@W_fe+b) ; np0 = f1@We0_feat+be0 (fused) ----
    k_gemm<4, false, true, true, 0, true, 1, false, false><<<TN, 256, GEMM_SMEM>>>(
        features, nullptr, points, centers, labels, rel,
        W_fe, b_fe, nullptr, nullptr, f1, We0 + 192, be0, np, Nn);

    // ---- GNN layer 0 on N ----
    k_agg<<<(Nn + 7) / 8, 256>>>(offs0, csr0, points, (const float2*)np, We0, (float2*)agg, Nn);
    k_gemm<64, false, false, false, 1, true, 1, false, false><<<TN, 256, GEMM_SMEM>>>(
        agg, nullptr, nullptr, nullptr, nullptr, rel,
        Wu0, bu0, f1, nullptr, f2, We1 + 192, be1, np, Nn);   // f2 ; np1

    // ---- GNN layer 1 on N, fused with h = relu([f21,rel]@W_m1+b_m1) ----
    k_agg<<<(Nn + 7) / 8, 256>>>(offs0, csr0, points, (const float2*)np, We1, (float2*)agg, Nn);
    k_gemm<64, false, false, false, 1, true, 1, true, true><<<TN, 256, GEMM_SMEM>>>(
        agg, nullptr, nullptr, nullptr, nullptr, rel,
        Wu1, bu1, f2, nullptr, f21, W_m1, b_m1, np, Nn);      // f21 ; h -> np

    // ---- cluster branch ----
    k_segsum<<<(Mm + 7) / 8, 256>>>(offsL, csrL, (const float2*)np, (float2*)mA, Mm);
    k_gemm<64, false, false, false, 0, true, 1, false, false><<<TM, 256, GEMM_SMEM>>>(
        mA, nullptr, nullptr, nullptr, nullptr, rel,
        W_m2, b_m2, nullptr, nullptr, mB, gWe0 + 192, gbe0, mnp, Mm);   // f3=mB ; npM0
    k_agg<<<(Mm + 7) / 8, 256>>>(offs1, csr1, centers, (const float2*)mnp, gWe0, (float2*)magg, Mm);
    k_gemm<64, false, false, false, 1, true, 1, false, false><<<TM, 256, GEMM_SMEM>>>(
        magg, nullptr, nullptr, nullptr, nullptr, rel,
        gWu0, gbu0, mB, nullptr, mA, gWe1 + 192, gbe1, mnp, Mm);        // f4=mA ; npM1
    k_agg<<<(Mm + 7) / 8, 256>>>(offs1, csr1, centers, (const float2*)mnp, gWe1, (float2*)magg, Mm);
    k_gemm<64, false, false, false, 1, true, 0, false, false><<<TM, 256, GEMM_SMEM>>>(
        magg, nullptr, nullptr, nullptr, nullptr, rel,
        gWu1, gbu1, mA, nullptr, mB, nullptr, nullptr, nullptr, Mm);    // f4_1=mB

    // ---- f5 = relu([f4_1[labels], rel]@W_l+b_l) ; np2 fused ----
    k_gemm<64, true, false, true, 0, true, 1, false, false><<<TN, 256, GEMM_SMEM>>>(
        mB, labels, nullptr, nullptr, nullptr, rel,
        W_l, b_l, nullptr, nullptr, f5, We2 + 192, be2, np, Nn);

    // ---- GNN layer 2 on N: f6 = relu(agg@Wu2+bu2)+f5+f21 ; np3 fused ----
    k_agg<<<(Nn + 7) / 8, 256>>>(offs0, csr0, points, (const float2*)np, We2, (float2*)agg, Nn);
    k_gemm<64, false, false, false, 2, true, 1, false, false><<<TN, 256, GEMM_SMEM>>>(
        agg, nullptr, nullptr, nullptr, nullptr, rel,
        Wu2, bu2, f5, f21, f6, We3 + 192, be3, np, Nn);

    // ---- GNN layer 3 on N fused with classifier ----
    k_agg<<<(Nn + 7) / 8, 256>>>(offs0, csr0, points, (const float2*)np, We3, (float2*)agg, Nn);
    k_gemm<64, false, false, false, 2, false, 2, false, false><<<TN, 256, GEMM_SMEM>>>(
        agg, nullptr, nullptr, nullptr, nullptr, rel,
        Wu3, bu3, f6, f2, nullptr, W_c, b_c, out, Nn);
}

// round 5
// speedup vs baseline: 1.5559x; 1.2822x over previous
#include <cuda_runtime.h>
#include <cstddef>
#include <cstdint>

// ---------------- problem constants ----------------
constexpr int Nn  = 100000;
constexpr int Mm  = 12500;
constexpr int E0n = 1600000;
constexpr int E1n = 400000;

constexpr int NB0 = (Nn + 1023) / 1024;   // 98
constexpr int NB1 = (Mm + 1023) / 1024;   // 13
constexpr int NBL = (Mm + 1023) / 1024;   // 13
constexpr int TOTB = NB0 + NB1 + NBL;     // 124

constexpr size_t F_N64 = (size_t)Nn * 64;
constexpr size_t F_M64 = (size_t)Mm * 64;
constexpr size_t pad16(size_t x) { return (x + 15) & ~(size_t)15; }

// arena (floats)
constexpr size_t OFF_F1   = 0;
constexpr size_t OFF_F2   = OFF_F1  + F_N64;
constexpr size_t OFF_F21  = OFF_F2  + F_N64;
constexpr size_t OFF_F5   = OFF_F21 + F_N64;
constexpr size_t OFF_F6   = OFF_F5  + F_N64;
constexpr size_t OFF_NP   = OFF_F6  + F_N64;
constexpr size_t OFF_AGG  = OFF_NP  + F_N64;
constexpr size_t OFF_REL  = OFF_AGG + F_N64;
constexpr size_t OFF_MA   = OFF_REL + pad16((size_t)Nn * 3);
constexpr size_t OFF_MB   = OFF_MA  + F_M64;
constexpr size_t OFF_MNP  = OFF_MB  + F_M64;
constexpr size_t OFF_MAGG = OFF_MNP + F_M64;
// int region
constexpr size_t OFF_CNT0  = OFF_MAGG + F_M64;
constexpr size_t OFF_CNT1  = OFF_CNT0  + pad16(Nn);
constexpr size_t OFF_CNTL  = OFF_CNT1  + pad16(Mm);
constexpr size_t OFF_OFFS0 = OFF_CNTL  + pad16(Mm);
constexpr size_t OFF_CUR0  = OFF_OFFS0 + pad16(Nn + 1);
constexpr size_t OFF_CSR0  = OFF_CUR0  + pad16(Nn);
constexpr size_t OFF_OFFS1 = OFF_CSR0  + pad16(E0n);
constexpr size_t OFF_CUR1  = OFF_OFFS1 + pad16(Mm + 1);
constexpr size_t OFF_CSR1  = OFF_CUR1  + pad16(Mm);
constexpr size_t OFF_OFFSL = OFF_CSR1  + pad16(E1n);
constexpr size_t OFF_CURL  = OFF_OFFSL + pad16(Mm + 1);
constexpr size_t OFF_CSRL  = OFF_CURL  + pad16(Mm);
constexpr size_t OFF_BSUM  = OFF_CSRL  + pad16(Nn);
constexpr size_t ARENA_SZ  = OFF_BSUM  + pad16(TOTB);

__device__ __align__(256) static float g_arena[ARENA_SZ];

// ---------------- helpers ----------------
__device__ __forceinline__ void ffma2(unsigned long long& d, unsigned long long a, unsigned long long b) {
    asm("fma.rn.f32x2 %0, %1, %2, %0;" : "+l"(d) : "l"(a), "l"(b));
}
__device__ __forceinline__ float2 up2(unsigned long long x) {
    float2 f;
    asm("mov.b64 {%0, %1}, %2;" : "=f"(f.x), "=f"(f.y) : "l"(x));
    return f;
}

// ---------------- CSR build ----------------
__global__ void k_hist(const int2* __restrict__ edges, int* __restrict__ cnt, int E) {
    int e = blockIdx.x * blockDim.x + threadIdx.x;
    if (e < E) atomicAdd(&cnt[edges[e].y], 1);
}
__global__ void k_histL(const int* __restrict__ lab, int* __restrict__ cnt, int n) {
    int i = blockIdx.x * blockDim.x + threadIdx.x;
    if (i < n) atomicAdd(&cnt[lab[i]], 1);
}

// Pass A: per-block scan of 1024-element tiles of the 3 count arrays.
__global__ void k_scanA(const int* __restrict__ c0, int* __restrict__ o0,
                        const int* __restrict__ c1, int* __restrict__ o1,
                        const int* __restrict__ c2, int* __restrict__ o2,
                        int* __restrict__ bsum) {
    const int b = blockIdx.x;
    const int* cnt; int* offs; int n; int lb;
    if (b < NB0)            { cnt = c0; offs = o0; n = Nn; lb = b; }
    else if (b < NB0 + NB1) { cnt = c1; offs = o1; n = Mm; lb = b - NB0; }
    else                    { cnt = c2; offs = o2; n = Mm; lb = b - NB0 - NB1; }
    __shared__ int s[1024];
    int t = threadIdx.x;
    int g = lb * 1024 + t;
    int v = (g < n) ? cnt[g] : 0;
    s[t] = v;
    __syncthreads();
    #pragma unroll
    for (int off = 1; off < 1024; off <<= 1) {
        int u = (t >= off) ? s[t - off] : 0;
        __syncthreads();
        s[t] += u;
        __syncthreads();
    }
    if (g < n) offs[g] = s[t] - v;
    if (t == 1023) bsum[b] = s[1023];
}

// Pass B: 1 block, warp per segment.
__global__ void k_scanB(int* __restrict__ bsum, int* __restrict__ o0,
                        int* __restrict__ o1, int* __restrict__ o2) {
    int w = threadIdx.x >> 5, lane = threadIdx.x & 31;
    int base, nb; int* offs; int n;
    if (w == 0)      { base = 0;         nb = NB0; offs = o0; n = Nn; }
    else if (w == 1) { base = NB0;       nb = NB1; offs = o1; n = Mm; }
    else             { base = NB0 + NB1; nb = NBL; offs = o2; n = Mm; }
    int carry = 0;
    for (int i0 = 0; i0 < nb; i0 += 32) {
        int i = i0 + lane;
        int orig = (i < nb) ? bsum[base + i] : 0;
        int v = orig;
        #pragma unroll
        for (int d = 1; d < 32; d <<= 1) {
            int u = __shfl_up_sync(0xffffffffu, v, d);
            if (lane >= d) v += u;
        }
        if (i < nb) bsum[base + i] = carry + v - orig;
        carry += __shfl_sync(0xffffffffu, v, 31);
    }
    if (lane == 0) offs[n] = carry;
}

// Pass C: add block offsets, write offs and cur.
__global__ void k_scanC(int* __restrict__ o0, int* __restrict__ u0,
                        int* __restrict__ o1, int* __restrict__ u1,
                        int* __restrict__ o2, int* __restrict__ u2,
                        const int* __restrict__ bsum) {
    const int b = blockIdx.x;
    int* offs; int* cur; int n; int lb;
    if (b < NB0)            { offs = o0; cur = u0; n = Nn; lb = b; }
    else if (b < NB0 + NB1) { offs = o1; cur = u1; n = Mm; lb = b - NB0; }
    else                    { offs = o2; cur = u2; n = Mm; lb = b - NB0 - NB1; }
    int g = lb * 1024 + threadIdx.x;
    if (g < n) {
        int val = offs[g] + bsum[b];
        offs[g] = val;
        cur[g]  = val;
    }
}

__global__ void k_scatter(const int2* __restrict__ edges, int* __restrict__ cur,
                          int* __restrict__ csrc, int E) {
    int e = blockIdx.x * blockDim.x + threadIdx.x;
    if (e < E) {
        int2 ed = edges[e];
        int p = atomicAdd(&cur[ed.y], 1);
        csrc[p] = ed.x;
    }
}
__global__ void k_scatterL(const int* __restrict__ lab, int* __restrict__ cur,
                           int* __restrict__ idx, int n) {
    int i = blockIdx.x * blockDim.x + threadIdx.x;
    if (i < n) {
        int p = atomicAdd(&cur[lab[i]], 1);
        idx[p] = i;
    }
}

// ---------------- edge aggregation ----------------
// t2[s] already contains np[s] + pos[s]@Wp, so per edge: pure segment max.
// agg[d][c] = max(0, max_s t2[s][c] - pos[d]@Wp[c])
__global__ void k_agg(const int* __restrict__ offs, const int* __restrict__ csrc,
                      const float* __restrict__ pos, const float2* __restrict__ t2,
                      const float* __restrict__ Wp, float2* __restrict__ agg, int n) {
    int lane = threadIdx.x & 31;
    int d = (blockIdx.x * blockDim.x + threadIdx.x) >> 5;
    if (d >= n) return;
    int c0 = 2 * lane, c1 = c0 + 1;
    float px = pos[3 * d], py = pos[3 * d + 1], pz = pos[3 * d + 2];
    float pdx = fmaf(px, Wp[c0], fmaf(py, Wp[64 + c0], pz * Wp[128 + c0]));
    float pdy = fmaf(px, Wp[c1], fmaf(py, Wp[64 + c1], pz * Wp[128 + c1]));
    int s0 = offs[d], s1 = offs[d + 1];
    float mx = -3.4e38f, my = -3.4e38f;
    int e = s0;
    for (; e + 4 <= s1; e += 4) {
        int sa = csrc[e], sb = csrc[e + 1], sc = csrc[e + 2], sd = csrc[e + 3];
        float2 va = t2[(size_t)sa * 32 + lane];
        float2 vb = t2[(size_t)sb * 32 + lane];
        float2 vc = t2[(size_t)sc * 32 + lane];
        float2 vd = t2[(size_t)sd * 32 + lane];
        mx = fmaxf(fmaxf(mx, va.x), fmaxf(vb.x, fmaxf(vc.x, vd.x)));
        my = fmaxf(fmaxf(my, va.y), fmaxf(vb.y, fmaxf(vc.y, vd.y)));
    }
    for (; e < s1; e++) {
        int s = csrc[e];
        float2 v = t2[(size_t)s * 32 + lane];
        mx = fmaxf(mx, v.x);
        my = fmaxf(my, v.y);
    }
    agg[(size_t)d * 32 + lane] = make_float2(fmaxf(mx - pdx, 0.f), fmaxf(my - pdy, 0.f));
}

// segment sum via label-CSR: warp per cluster
__global__ void k_segsum(const int* __restrict__ offs, const int* __restrict__ idx,
                         const float2* __restrict__ h, float2* __restrict__ c, int m) {
    int lane = threadIdx.x & 31;
    int d = (blockIdx.x * blockDim.x + threadIdx.x) >> 5;
    if (d >= m) return;
    int s0 = offs[d], s1 = offs[d + 1];
    float sx = 0.f, sy = 0.f;
    int e = s0;
    for (; e + 2 <= s1; e += 2) {
        int pa = idx[e], pb = idx[e + 1];
        float2 va = h[(size_t)pa * 32 + lane];
        float2 vb = h[(size_t)pb * 32 + lane];
        sx += va.x + vb.x; sy += va.y + vb.y;
    }
    for (; e < s1; e++) {
        int p = idx[e];
        float2 v = h[(size_t)p * 32 + lane];
        sx += v.x; sy += v.y;
    }
    c[(size_t)d * 32 + lane] = make_float2(sx, sy);
}

// ---------------- unified GEMM kernel ----------------
// out1 = relu(A @ W1[0:K1] + b1 (+ rel @ W1[K1:K1+3])) (+res1)(+res2)
// FUSE==1: out2 = out1 @ W2 + b2 (+ vec3 @ Wr2)  where vec3 = pos (REL2POS) or rel
// FUSE==2: out2 = out1 @ W2(64x8) + b2  (classifier)
template<int K1, bool GATHER, bool MAKEREL, bool REL1, int NRES, bool STORE1,
         int FUSE, bool REL2, bool REL2POS, bool RELU2>
__global__ __launch_bounds__(256)
void k_gemm(const float* __restrict__ in, const int* __restrict__ gidx,
            const float* __restrict__ points, const float* __restrict__ centers,
            const int* __restrict__ labels, float* __restrict__ relg,
            const float* __restrict__ posv,
            const float* __restrict__ W1, const float* __restrict__ b1,
            const float* __restrict__ res1, const float* __restrict__ res2,
            float* __restrict__ out1,
            const float* __restrict__ W2, const float* __restrict__ Wr2,
            const float* __restrict__ b2,
            float* __restrict__ out2, int n) {
    extern __shared__ float2 sAd[];          // [KC][66] duplicated A: {a,a}  (KC<=32)
    __shared__ float sW[64 * 64];
    __shared__ float sWr1[192];
    __shared__ float sWr2[192];
    __shared__ float sRel[192];
    __shared__ float sPos[192];

    constexpr int KC = (K1 < 32) ? K1 : 32;
    constexpr bool NEED_REL = MAKEREL || REL1 || (REL2 && !REL2POS);

    const int tid = threadIdx.x;
    const int row0 = blockIdx.x * 64;

    for (int i = tid; i < K1 * 64; i += 256) sW[i] = W1[i];
    if (REL1)
        for (int i = tid; i < 192; i += 256) sWr1[i] = W1[K1 * 64 + i];
    if (MAKEREL) {
        if (tid < 64) {
            int row = row0 + tid;
            float rx = 0.f, ry = 0.f, rz = 0.f;
            if (row < n) {
                int l = labels[row];
                rx = points[3 * row]     - centers[3 * l];
                ry = points[3 * row + 1] - centers[3 * l + 1];
                rz = points[3 * row + 2] - centers[3 * l + 2];
                relg[3 * row] = rx; relg[3 * row + 1] = ry; relg[3 * row + 2] = rz;
            }
            sRel[tid * 3] = rx; sRel[tid * 3 + 1] = ry; sRel[tid * 3 + 2] = rz;
        }
    } else if (NEED_REL) {
        if (tid < 64) {
            int row = row0 + tid;
            float rx = 0.f, ry = 0.f, rz = 0.f;
            if (row < n) { rx = relg[3 * row]; ry = relg[3 * row + 1]; rz = relg[3 * row + 2]; }
            sRel[tid * 3] = rx; sRel[tid * 3 + 1] = ry; sRel[tid * 3 + 2] = rz;
        }
    }
    if (REL2 && REL2POS) {
        if (tid >= 64 && tid < 128) {
            int r = tid - 64;
            int row = row0 + r;
            float rx = 0.f, ry = 0.f, rz = 0.f;
            if (row < n) { rx = posv[3 * row]; ry = posv[3 * row + 1]; rz = posv[3 * row + 2]; }
            sPos[r * 3] = rx; sPos[r * 3 + 1] = ry; sPos[r * 3 + 2] = rz;
        }
    }

    const int tx = tid & 15, ty = tid >> 4;
    unsigned long long acc[4][2];
    #pragma unroll
    for (int r = 0; r < 4; r++) { acc[r][0] = 0ULL; acc[r][1] = 0ULL; }

    // ---- first GEMM, A chunked over K ----
    for (int kc = 0; kc < K1; kc += KC) {
        __syncthreads();
        for (int i = tid; i < KC * 64; i += 256) {
            int r = i / KC, k = i - r * KC;
            int row = row0 + r;
            float v = 0.f;
            if (row < n) {
                int sr = GATHER ? gidx[row] : row;
                v = in[(size_t)sr * K1 + kc + k];
            }
            sAd[k * 66 + r] = make_float2(v, v);
        }
        __syncthreads();
        #pragma unroll 16
        for (int k = 0; k < KC; k++) {
            const ulonglong2 a01 = *reinterpret_cast<const ulonglong2*>(&sAd[k * 66 + ty * 4]);
            const ulonglong2 a23 = *reinterpret_cast<const ulonglong2*>(&sAd[k * 66 + ty * 4 + 2]);
            const ulonglong2 bv  = *reinterpret_cast<const ulonglong2*>(&sW[(kc + k) * 64 + tx * 4]);
            ffma2(acc[0][0], a01.x, bv.x); ffma2(acc[0][1], a01.x, bv.y);
            ffma2(acc[1][0], a01.y, bv.x); ffma2(acc[1][1], a01.y, bv.y);
            ffma2(acc[2][0], a23.x, bv.x); ffma2(acc[2][1], a23.x, bv.y);
            ffma2(acc[3][0], a23.y, bv.x); ffma2(acc[3][1], a23.y, bv.y);
        }
    }

    // ---- epilogue 1 ----
    float v[4][4];
    const float b1x = b1[tx * 4], b1y = b1[tx * 4 + 1], b1z = b1[tx * 4 + 2], b1w = b1[tx * 4 + 3];
    #pragma unroll
    for (int r = 0; r < 4; r++) {
        float2 p0 = up2(acc[r][0]), p1 = up2(acc[r][1]);
        v[r][0] = p0.x + b1x; v[r][1] = p0.y + b1y;
        v[r][2] = p1.x + b1z; v[r][3] = p1.y + b1w;
        if (REL1) {
            int lr = ty * 4 + r;
            float rx = sRel[lr * 3], ry = sRel[lr * 3 + 1], rz = sRel[lr * 3 + 2];
            #pragma unroll
            for (int c = 0; c < 4; c++) {
                int col = tx * 4 + c;
                v[r][c] += rx * sWr1[col] + ry * sWr1[64 + col] + rz * sWr1[128 + col];
            }
        }
        #pragma unroll
        for (int c = 0; c < 4; c++) v[r][c] = fmaxf(v[r][c], 0.f);
        int row = row0 + ty * 4 + r;
        if (row < n) {
            size_t base = (size_t)row * 64 + tx * 4;
            if (NRES >= 1) {
                const float4 r1 = *reinterpret_cast<const float4*>(&res1[base]);
                v[r][0] += r1.x; v[r][1] += r1.y; v[r][2] += r1.z; v[r][3] += r1.w;
            }
            if (NRES >= 2) {
                const float4 r2 = *reinterpret_cast<const float4*>(&res2[base]);
                v[r][0] += r2.x; v[r][1] += r2.y; v[r][2] += r2.z; v[r][3] += r2.w;
            }
            if (STORE1) {
                float4 o = { v[r][0], v[r][1], v[r][2], v[r][3] };
                *reinterpret_cast<float4*>(&out1[base]) = o;
            }
        } else {
            v[r][0] = v[r][1] = v[r][2] = v[r][3] = 0.f;
        }
    }

    if (FUSE == 0) return;

    // ---- second GEMM: input = out1 tile (registers v), staged in halves ----
    unsigned long long acc2[4][2];
    float accc[2];
    if (FUSE == 1) {
        #pragma unroll
        for (int r = 0; r < 4; r++) { acc2[r][0] = 0ULL; acc2[r][1] = 0ULL; }
    } else {
        accc[0] = b2[tid & 7]; accc[1] = accc[0];
    }

    #pragma unroll
    for (int half = 0; half < 2; half++) {
        __syncthreads();
        if (half == 0) {
            if (FUSE == 1) {
                for (int i = tid; i < 4096; i += 256) sW[i] = W2[i];
                if (REL2)
                    for (int i = tid; i < 192; i += 256) sWr2[i] = Wr2[i];
            } else {
                for (int i = tid; i < 512; i += 256) sW[i] = W2[i];
            }
        }
        if ((tx >> 3) == half) {
            #pragma unroll
            for (int c = 0; c < 4; c++)
                #pragma unroll
                for (int r = 0; r < 4; r++)
                    sAd[(tx * 4 + c - half * 32) * 66 + (ty * 4 + r)] = make_float2(v[r][c], v[r][c]);
        }
        __syncthreads();
        if (FUSE == 1) {
            #pragma unroll 16
            for (int k = 0; k < 32; k++) {
                const ulonglong2 a01 = *reinterpret_cast<const ulonglong2*>(&sAd[k * 66 + ty * 4]);
                const ulonglong2 a23 = *reinterpret_cast<const ulonglong2*>(&sAd[k * 66 + ty * 4 + 2]);
                const ulonglong2 bv  = *reinterpret_cast<const ulonglong2*>(&sW[(half * 32 + k) * 64 + tx * 4]);
                ffma2(acc2[0][0], a01.x, bv.x); ffma2(acc2[0][1], a01.x, bv.y);
                ffma2(acc2[1][0], a01.y, bv.x); ffma2(acc2[1][1], a01.y, bv.y);
                ffma2(acc2[2][0], a23.x, bv.x); ffma2(acc2[2][1], a23.x, bv.y);
                ffma2(acc2[3][0], a23.y, bv.x); ffma2(acc2[3][1], a23.y, bv.y);
            }
        } else {
            int r8 = tid >> 3, cls = tid & 7;
            #pragma unroll
            for (int h = 0; h < 2; h++) {
                int lr = (h == 0) ? r8 : (r8 + 32);
                float a = accc[h];
                #pragma unroll 16
                for (int k = 0; k < 32; k++)
                    a = fmaf(sAd[k * 66 + lr].x, sW[(half * 32 + k) * 8 + cls], a);
                accc[h] = a;
            }
        }
    }

    if (FUSE == 1) {
        const float b2x = b2[tx * 4], b2y = b2[tx * 4 + 1], b2z = b2[tx * 4 + 2], b2w = b2[tx * 4 + 3];
        #pragma unroll
        for (int r = 0; r < 4; r++) {
            int row = row0 + ty * 4 + r;
            if (row >= n) continue;
            float2 p0 = up2(acc2[r][0]), p1 = up2(acc2[r][1]);
            float w0 = p0.x + b2x, w1 = p0.y + b2y, w2 = p1.x + b2z, w3 = p1.y + b2w;
            if (REL2) {
                int lr = ty * 4 + r;
                const float* sv = REL2POS ? sPos : sRel;
                float rx = sv[lr * 3], ry = sv[lr * 3 + 1], rz = sv[lr * 3 + 2];
                int col = tx * 4;
                w0 += rx * sWr2[col]     + ry * sWr2[64 + col]     + rz * sWr2[128 + col];
                w1 += rx * sWr2[col + 1] + ry * sWr2[64 + col + 1] + rz * sWr2[128 + col + 1];
                w2 += rx * sWr2[col + 2] + ry * sWr2[64 + col + 2] + rz * sWr2[128 + col + 2];
                w3 += rx * sWr2[col + 3] + ry * sWr2[64 + col + 3] + rz * sWr2[128 + col + 3];
            }
            if (RELU2) {
                w0 = fmaxf(w0, 0.f); w1 = fmaxf(w1, 0.f);
                w2 = fmaxf(w2, 0.f); w3 = fmaxf(w3, 0.f);
            }
            float4 o = { w0, w1, w2, w3 };
            *reinterpret_cast<float4*>(&out2[(size_t)row * 64 + tx * 4]) = o;
        }
    } else {
        int r8 = tid >> 3, cls = tid & 7;
        #pragma unroll
        for (int h = 0; h < 2; h++) {
            int row = row0 + ((h == 0) ? r8 : (r8 + 32));
            if (row < n) out2[(size_t)row * 8 + cls] = accc[h];
        }
    }
}

// ---------------- host orchestration ----------------
constexpr int GEMM_SMEM = 32 * 66 * (int)sizeof(float2);   // 16896 dynamic

extern "C" void kernel_launch(void* const* d_in, const int* in_sizes, int n_in,
                              void* d_out, int out_size) {
    (void)in_sizes; (void)n_in; (void)out_size;
    float* A = nullptr;
    cudaGetSymbolAddress((void**)&A, g_arena);

    float* f1   = A + OFF_F1;
    float* f2   = A + OFF_F2;
    float* f21  = A + OFF_F21;
    float* f5   = A + OFF_F5;
    float* f6   = A + OFF_F6;
    float* np   = A + OFF_NP;
    float* agg  = A + OFF_AGG;
    float* rel  = A + OFF_REL;
    float* mA   = A + OFF_MA;
    float* mB   = A + OFF_MB;
    float* mnp  = A + OFF_MNP;
    float* magg = A + OFF_MAGG;
    int* cnt0  = (int*)(A + OFF_CNT0);
    int* cnt1  = (int*)(A + OFF_CNT1);
    int* cntL  = (int*)(A + OFF_CNTL);
    int* offs0 = (int*)(A + OFF_OFFS0);
    int* cur0  = (int*)(A + OFF_CUR0);
    int* csr0  = (int*)(A + OFF_CSR0);
    int* offs1 = (int*)(A + OFF_OFFS1);
    int* cur1  = (int*)(A + OFF_CUR1);
    int* csr1  = (int*)(A + OFF_CSR1);
    int* offsL = (int*)(A + OFF_OFFSL);
    int* curL  = (int*)(A + OFF_CURL);
    int* csrL  = (int*)(A + OFF_CSRL);
    int* bsum  = (int*)(A + OFF_BSUM);

    const float* features = (const float*)d_in[0];
    const float* points   = (const float*)d_in[1];
    const float* centers  = (const float*)d_in[2];
    const int*   l0       = (const int*)d_in[3];
    const int*   l1       = (const int*)d_in[4];
    const int*   labels   = (const int*)d_in[5];
    const float* W_fe     = (const float*)d_in[6];
    const float* b_fe     = (const float*)d_in[7];
    const float* mini_We  = (const float*)d_in[8];
    const float* mini_be  = (const float*)d_in[9];
    const float* mini_Wu  = (const float*)d_in[10];
    const float* mini_bu  = (const float*)d_in[11];
    const float* W_m1     = (const float*)d_in[12];
    const float* b_m1     = (const float*)d_in[13];
    const float* W_m2     = (const float*)d_in[14];
    const float* b_m2     = (const float*)d_in[15];
    const float* gnn_We   = (const float*)d_in[16];
    const float* gnn_be   = (const float*)d_in[17];
    const float* gnn_Wu   = (const float*)d_in[18];
    const float* gnn_bu   = (const float*)d_in[19];
    const float* W_l      = (const float*)d_in[20];
    const float* b_l      = (const float*)d_in[21];
    const float* W_c      = (const float*)d_in[22];
    const float* b_c      = (const float*)d_in[23];
    float* out = (float*)d_out;

    const int TN = (Nn + 63) / 64;   // 1563
    const int TM = (Mm + 63) / 64;   // 196

    const float* We0 = mini_We;               const float* be0 = mini_be;
    const float* We1 = mini_We + 67 * 64;     const float* be1 = mini_be + 64;
    const float* We2 = mini_We + 2 * 67 * 64; const float* be2 = mini_be + 128;
    const float* We3 = mini_We + 3 * 67 * 64; const float* be3 = mini_be + 192;
    const float* Wu0 = mini_Wu;               const float* bu0 = mini_bu;
    const float* Wu1 = mini_Wu + 4096;        const float* bu1 = mini_bu + 64;
    const float* Wu2 = mini_Wu + 2 * 4096;    const float* bu2 = mini_bu + 128;
    const float* Wu3 = mini_Wu + 3 * 4096;    const float* bu3 = mini_bu + 192;
    const float* gWe0 = gnn_We;               const float* gbe0 = gnn_be;
    const float* gWe1 = gnn_We + 67 * 64;     const float* gbe1 = gnn_be + 64;
    const float* gWu0 = gnn_Wu;               const float* gbu0 = gnn_bu;
    const float* gWu1 = gnn_Wu + 4096;        const float* gbu1 = gnn_bu + 64;

    // ---- CSR builds ----
    cudaMemsetAsync((void*)cnt0, 0, (OFF_OFFS0 - OFF_CNT0) * sizeof(float));
    k_hist<<<(E0n + 255) / 256, 256>>>((const int2*)l0, cnt0, E0n);
    k_hist<<<(E1n + 255) / 256, 256>>>((const int2*)l1, cnt1, E1n);
    k_histL<<<(Nn + 255) / 256, 256>>>(labels, cntL, Nn);
    k_scanA<<<TOTB, 1024>>>(cnt0, offs0, cnt1, offs1, cntL, offsL, bsum);
    k_scanB<<<1, 96>>>(bsum, offs0, offs1, offsL);
    k_scanC<<<TOTB, 1024>>>(offs0, cur0, offs1, cur1, offsL, curL, bsum);
    k_scatter<<<(E0n + 255) / 256, 256>>>((const int2*)l0, cur0, csr0, E0n);
    k_scatter<<<(E1n + 255) / 256, 256>>>((const int2*)l1, cur1, csr1, E1n);
    k_scatterL<<<(Nn + 255) / 256, 256>>>(labels, curL, csrL, Nn);

    // ---- f1 = relu([feat,rel]@W_fe+b) ; t0 = f1@We0_feat+be0 + pos@We0_pos ----
    k_gemm<4, false, true, true, 0, true, 1, true, true, false><<<TN, 256, GEMM_SMEM>>>(
        features, nullptr, points, centers, labels, rel, points,
        W_fe, b_fe, nullptr, nullptr, f1, We0 + 192, We0, be0, np, Nn);

    // ---- GNN layer 0 on N ----
    k_agg<<<(Nn + 7) / 8, 256>>>(offs0, csr0, points, (const float2*)np, We0, (float2*)agg, Nn);
    k_gemm<64, false, false, false, 1, true, 1, true, true, false><<<TN, 256, GEMM_SMEM>>>(
        agg, nullptr, nullptr, nullptr, nullptr, rel, points,
        Wu0, bu0, f1, nullptr, f2, We1 + 192, We1, be1, np, Nn);   // f2 ; t1

    // ---- GNN layer 1 on N, fused with h = relu([f21,rel]@W_m1+b_m1) ----
    k_agg<<<(Nn + 7) / 8, 256>>>(offs0, csr0, points, (const float2*)np, We1, (float2*)agg, Nn);
    k_gemm<64, false, false, false, 1, true, 1, true, false, true><<<TN, 256, GEMM_SMEM>>>(
        agg, nullptr, nullptr, nullptr, nullptr, rel, nullptr,
        Wu1, bu1, f2, nullptr, f21, W_m1, W_m1 + 4096, b_m1, np, Nn);   // f21 ; h

    // ---- cluster branch ----
    k_segsum<<<(Mm + 7) / 8, 256>>>(offsL, csrL, (const float2*)np, (float2*)mA, Mm);
    k_gemm<64, false, false, false, 0, true, 1, true, true, false><<<TM, 256, GEMM_SMEM>>>(
        mA, nullptr, nullptr, nullptr, nullptr, rel, centers,
        W_m2, b_m2, nullptr, nullptr, mB, gWe0 + 192, gWe0, gbe0, mnp, Mm);   // f3 ; tM0
    k_agg<<<(Mm + 7) / 8, 256>>>(offs1, csr1, centers, (const float2*)mnp, gWe0, (float2*)magg, Mm);
    k_gemm<64, false, false, false, 1, true, 1, true, true, false><<<TM, 256, GEMM_SMEM>>>(
        magg, nullptr, nullptr, nullptr, nullptr, rel, centers,
        gWu0, gbu0, mB, nullptr, mA, gWe1 + 192, gWe1, gbe1, mnp, Mm);        // f4 ; tM1
    k_agg<<<(Mm + 7) / 8, 256>>>(offs1, csr1, centers, (const float2*)mnp, gWe1, (float2*)magg, Mm);
    k_gemm<64, false, false, false, 1, true, 0, false, false, false><<<TM, 256, GEMM_SMEM>>>(
        magg, nullptr, nullptr, nullptr, nullptr, rel, nullptr,
        gWu1, gbu1, mA, nullptr, mB, nullptr, nullptr, nullptr, nullptr, Mm); // f4_1

    // ---- f5 = relu([f4_1[labels], rel]@W_l+b_l) ; t2 fused ----
    k_gemm<64, true, false, true, 0, true, 1, true, true, false><<<TN, 256, GEMM_SMEM>>>(
        mB, labels, nullptr, nullptr, nullptr, rel, points,
        W_l, b_l, nullptr, nullptr, f5, We2 + 192, We2, be2, np, Nn);

    // ---- GNN layer 2 on N: f6 = relu(agg@Wu2+bu2)+f5+f21 ; t3 fused ----
    k_agg<<<(Nn + 7) / 8, 256>>>(offs0, csr0, points, (const float2*)np, We2, (float2*)agg, Nn);
    k_gemm<64, false, false, false, 2, true, 1, true, true, false><<<TN, 256, GEMM_SMEM>>>(
        agg, nullptr, nullptr, nullptr, nullptr, rel, points,
        Wu2, bu2, f5, f21, f6, We3 + 192, We3, be3, np, Nn);

    // ---- GNN layer 3 on N fused with classifier ----
    k_agg<<<(Nn + 7) / 8, 256>>>(offs0, csr0, points, (const float2*)np, We3, (float2*)agg, Nn);
    k_gemm<64, false, false, false, 2, false, 2, false, false, false><<<TN, 256, GEMM_SMEM>>>(
        agg, nullptr, nullptr, nullptr, nullptr, rel, nullptr,
        Wu3, bu3, f6, f2, nullptr, W_c, nullptr, b_c, out, Nn);
}